// round 1
// baseline (speedup 1.0000x reference)
#include <cuda_runtime.h>
#include <math.h>

// ---------------- problem constants ----------------
constexpr int BB   = 8;        // batch
constexpr int CC   = 512;      // channels
constexpr int SS   = 1024;     // H*W sequence length
constexpr int NHH  = 8;        // heads
constexpr int DHH  = 64;       // head dim
constexpr int NCC  = 77;       // cond tokens
constexpr int DCC  = 768;      // cond dim
constexpr int MM   = BB * SS;  // 8192 rows

// ---------------- scratch (__device__ globals, no allocs) ----------------
__device__ float g_t   [ (long)MM * CC ];          // 16 MB residual stream (b,s,c)
__device__ float g_tn  [ (long)MM * CC ];          // normed / misc
__device__ float g_q   [ (long)MM * CC ];
__device__ float g_k   [ (long)MM * CC ];
__device__ float g_v   [ (long)MM * CC ];
__device__ float g_ao  [ (long)MM * CC ];
__device__ float g_attn[ 64L * 1024 * 1024 ];      // 256 MB scores / GEGLU scratch
__device__ float g_ffh [ (long)MM * 4096 ];        // 128 MB FFN hidden
__device__ float g_stats[ 2 * BB * 32 ];           // groupnorm mean/rstd

// ---------------- reductions ----------------
__inline__ __device__ float warpSum(float v){
    #pragma unroll
    for (int o = 16; o > 0; o >>= 1) v += __shfl_xor_sync(0xffffffffu, v, o);
    return v;
}
__inline__ __device__ float warpMax(float v){
    #pragma unroll
    for (int o = 16; o > 0; o >>= 1) v = fmaxf(v, __shfl_xor_sync(0xffffffffu, v, o));
    return v;
}

// ---------------- groupnorm ----------------
// one block per (b, group): 16 channels * 1024 px = 16384 contiguous floats
__global__ void gn_stats_k(const float* __restrict__ x, float* __restrict__ stats){
    long base = (long)blockIdx.x * 16384;
    float s = 0.f, q = 0.f;
    for (int i = threadIdx.x; i < 16384; i += blockDim.x){
        float v = x[base + i];
        s += v; q += v * v;
    }
    __shared__ float shs[8], shq[8];
    s = warpSum(s); q = warpSum(q);
    int w = threadIdx.x >> 5, l = threadIdx.x & 31;
    if (l == 0){ shs[w] = s; shq[w] = q; }
    __syncthreads();
    if (threadIdx.x < 32){
        s = (l < 8) ? shs[l] : 0.f;
        q = (l < 8) ? shq[l] : 0.f;
        s = warpSum(s); q = warpSum(q);
        if (l == 0){
            float mean = s * (1.f / 16384.f);
            float var  = q * (1.f / 16384.f) - mean * mean;
            stats[2 * blockIdx.x]     = mean;
            stats[2 * blockIdx.x + 1] = rsqrtf(var + 1e-6f);
        }
    }
}

// normalize + transpose (b,c,p) -> (b,p,c)
__global__ void gn_apply_k(const float* __restrict__ x, const float* __restrict__ stats,
                           const float* __restrict__ gs, const float* __restrict__ gb,
                           float* __restrict__ out){
    long idx = (long)blockIdx.x * blockDim.x + threadIdx.x;
    if (idx >= (long)BB * CC * SS) return;
    int p = (int)(idx & 1023);
    int c = (int)((idx >> 10) & 511);
    int b = (int)(idx >> 19);
    int grp = b * 32 + (c >> 4);
    float mean = stats[2 * grp], rstd = stats[2 * grp + 1];
    float v = (x[idx] - mean) * rstd * gs[c] + gb[c];
    out[(((long)b << 10) + p) * CC + c] = v;
}

// ---------------- layernorm: 1 block (128 thr) per row of 512 ----------------
__global__ void layernorm_k(const float* __restrict__ in, const float* __restrict__ sc,
                            const float* __restrict__ bi, float* __restrict__ out){
    long row = blockIdx.x;
    const float4* x4 = (const float4*)(in + row * CC);
    float4 xv = x4[threadIdx.x];
    float s = xv.x + xv.y + xv.z + xv.w;
    float q = xv.x*xv.x + xv.y*xv.y + xv.z*xv.z + xv.w*xv.w;
    __shared__ float shs[4], shq[4];
    s = warpSum(s); q = warpSum(q);
    int w = threadIdx.x >> 5, l = threadIdx.x & 31;
    if (l == 0){ shs[w] = s; shq[w] = q; }
    __syncthreads();
    if (threadIdx.x < 32){
        float a = (l < 4) ? shs[l] : 0.f;
        float b2 = (l < 4) ? shq[l] : 0.f;
        a = warpSum(a); b2 = warpSum(b2);
        if (l == 0){ shs[0] = a; shq[0] = b2; }
    }
    __syncthreads();
    float mean = shs[0] * (1.f / 512.f);
    float rstd = rsqrtf(shq[0] * (1.f / 512.f) - mean * mean + 1e-5f);
    float4 sv = ((const float4*)sc)[threadIdx.x];
    float4 bv = ((const float4*)bi)[threadIdx.x];
    float4 o;
    o.x = (xv.x - mean) * rstd * sv.x + bv.x;
    o.y = (xv.y - mean) * rstd * sv.y + bv.y;
    o.z = (xv.z - mean) * rstd * sv.z + bv.z;
    o.w = (xv.w - mean) * rstd * sv.w + bv.w;
    ((float4*)(out + row * CC))[threadIdx.x] = o;
}

// ---------------- softmax: warp per row, row cached in registers ----------------
template<int NJ>
__global__ void softmax_k(float* __restrict__ p, long nrows, int ncols, int ld){
    long row = (long)blockIdx.x * (blockDim.x >> 5) + (threadIdx.x >> 5);
    if (row >= nrows) return;
    int lane = threadIdx.x & 31;
    float* r = p + row * (long)ld;
    float xs[NJ];
    float mx = -1e30f;
    #pragma unroll
    for (int t = 0; t < NJ; t++){
        int j = lane + t * 32;
        xs[t] = (j < ncols) ? r[j] : -1e30f;
        mx = fmaxf(mx, xs[t]);
    }
    mx = warpMax(mx);
    float sum = 0.f;
    #pragma unroll
    for (int t = 0; t < NJ; t++){ xs[t] = __expf(xs[t] - mx); sum += xs[t]; }
    sum = warpSum(sum);
    float inv = 1.f / sum;
    #pragma unroll
    for (int t = 0; t < NJ; t++){
        int j = lane + t * 32;
        if (j < ncols)      r[j] = xs[t] * inv;
        else if (j < ld)    r[j] = 0.f;   // zero pad so downstream GEMM reads clean zeros
    }
}

// ---------------- GEGLU ----------------
__global__ void geglu_k(const float* __restrict__ h, float* __restrict__ g){
    long idx = (long)blockIdx.x * blockDim.x + threadIdx.x;
    if (idx >= (long)MM * 2048) return;
    long m = idx >> 11;
    int  i = (int)(idx & 2047);
    float u    = h[m * 4096 + i];
    float gate = h[m * 4096 + 2048 + i];
    float ge = 0.5f * gate * (1.f + erff(gate * 0.70710678118654752f));
    g[idx] = u * ge;
}

// ---------------- final: transpose-back + x_in residual ----------------
__global__ void out_add_k(const float* __restrict__ z, const float* __restrict__ x,
                          float* __restrict__ out){
    long idx = (long)blockIdx.x * blockDim.x + threadIdx.x;
    if (idx >= (long)BB * CC * SS) return;
    int p = (int)(idx & 1023);
    int d = (int)((idx >> 10) & 511);
    long b = idx >> 19;
    out[idx] = z[((b << 10) + p) * CC + d] + x[idx];
}

// ---------------- generic tiled SGEMM ----------------
// C[m,n] = sum_k A[m,k] * (TB ? B[n,k] : B[k,n])  (+bias[n]) (+res[m,n])
// Batch z decomposed as (z/bdiv, z%bdiv) with independent strides.
template<int BM, int BN, int BK, bool TB>
__global__ void gemm_k(const float* __restrict__ A, const float* __restrict__ Bm,
                       const float* __restrict__ bias, const float* __restrict__ res,
                       float* __restrict__ C,
                       int M, int N, int K, int lda, int ldb, int ldc,
                       int bdiv, long sAo, long sAi, long sBo, long sBi, long sCo, long sCi){
    constexpr int TM = 8, TN = 8;
    constexpr int THREADS = (BM / TM) * (BN / TN);
    __shared__ float As[BK][BM];
    __shared__ float Bs[BK][BN];

    int z = blockIdx.z;
    long aoff = (long)(z / bdiv) * sAo + (long)(z % bdiv) * sAi;
    long boff = (long)(z / bdiv) * sBo + (long)(z % bdiv) * sBi;
    long coff = (long)(z / bdiv) * sCo + (long)(z % bdiv) * sCi;
    A += aoff; Bm += boff; C += coff;
    if (res) res += coff;

    int tid = threadIdx.x;
    int tx = tid % (BN / TN);
    int ty = tid / (BN / TN);
    int row0 = blockIdx.y * BM;
    int col0 = blockIdx.x * BN;

    float acc[TM][TN];
    #pragma unroll
    for (int u = 0; u < TM; u++)
        #pragma unroll
        for (int v = 0; v < TN; v++) acc[u][v] = 0.f;

    for (int kt = 0; kt < K; kt += BK){
        constexpr int AIT = (BM * BK) / THREADS;
        #pragma unroll
        for (int it = 0; it < AIT; ++it){
            int idx = tid + it * THREADS;
            int i = idx / BK, j = idx % BK;
            int m = row0 + i, k = kt + j;
            As[j][i] = (m < M && k < K) ? A[(long)m * lda + k] : 0.f;
        }
        constexpr int BIT = (BN * BK) / THREADS;
        #pragma unroll
        for (int it = 0; it < BIT; ++it){
            int idx = tid + it * THREADS;
            if (TB){
                int j = idx % BK, i = idx / BK;
                int n = col0 + i, k = kt + j;
                Bs[j][i] = (n < N && k < K) ? Bm[(long)n * ldb + k] : 0.f;
            } else {
                int i = idx % BN, j = idx / BN;
                int n = col0 + i, k = kt + j;
                Bs[j][i] = (n < N && k < K) ? Bm[(long)k * ldb + n] : 0.f;
            }
        }
        __syncthreads();
        #pragma unroll
        for (int kk = 0; kk < BK; kk++){
            float a[TM], b[TN];
            *(float4*)&a[0] = *(const float4*)&As[kk][ty * TM];
            *(float4*)&a[4] = *(const float4*)&As[kk][ty * TM + 4];
            *(float4*)&b[0] = *(const float4*)&Bs[kk][tx * TN];
            *(float4*)&b[4] = *(const float4*)&Bs[kk][tx * TN + 4];
            #pragma unroll
            for (int u = 0; u < TM; u++)
                #pragma unroll
                for (int v = 0; v < TN; v++)
                    acc[u][v] = fmaf(a[u], b[v], acc[u][v]);
        }
        __syncthreads();
    }

    #pragma unroll
    for (int u = 0; u < TM; u++){
        int m = row0 + ty * TM + u;
        if (m >= M) continue;
        #pragma unroll
        for (int v = 0; v < TN; v++){
            int n = col0 + tx * TN + v;
            if (n >= N) continue;
            float val = acc[u][v];
            if (bias) val += bias[n];
            if (res)  val += res[(long)m * ldc + n];
            C[(long)m * ldc + n] = val;
        }
    }
}

// ---------------- host-side helpers ----------------
static void gemm_big(const float* A, const float* W, const float* bias, const float* res,
                     float* C, int M, int N, int K, int lda, int ldb, int ldc){
    dim3 g((N + 127) / 128, (M + 127) / 128, 1);
    gemm_k<128,128,8,false><<<g, 256>>>(A, W, bias, res, C, M, N, K, lda, ldb, ldc,
                                        1, 0, 0, 0, 0, 0, 0);
}

extern "C" void kernel_launch(void* const* d_in, const int* in_sizes, int n_in,
                              void* d_out, int out_size){
    (void)in_sizes; (void)n_in; (void)out_size;
    const float* x      = (const float*)d_in[0];
    const float* cond   = (const float*)d_in[1];
    const float* gn_s   = (const float*)d_in[2];
    const float* gn_b   = (const float*)d_in[3];
    const float* pin_w  = (const float*)d_in[4];
    const float* pin_b  = (const float*)d_in[5];
    const float* pout_w = (const float*)d_in[6];
    const float* pout_b = (const float*)d_in[7];
    const float* ln1_s  = (const float*)d_in[8];
    const float* ln1_b  = (const float*)d_in[9];
    const float* sa_wq  = (const float*)d_in[10];
    const float* sa_wk  = (const float*)d_in[11];
    const float* sa_wv  = (const float*)d_in[12];
    const float* sa_wo  = (const float*)d_in[13];
    const float* sa_bo  = (const float*)d_in[14];
    const float* ln2_s  = (const float*)d_in[15];
    const float* ln2_b  = (const float*)d_in[16];
    const float* ca_wq  = (const float*)d_in[17];
    const float* ca_wk  = (const float*)d_in[18];
    const float* ca_wv  = (const float*)d_in[19];
    const float* ca_wo  = (const float*)d_in[20];
    const float* ca_bo  = (const float*)d_in[21];
    const float* ln3_s  = (const float*)d_in[22];
    const float* ln3_b  = (const float*)d_in[23];
    const float* ff_w1  = (const float*)d_in[24];
    const float* ff_b1  = (const float*)d_in[25];
    const float* ff_w2  = (const float*)d_in[26];
    const float* ff_b2  = (const float*)d_in[27];
    float* out = (float*)d_out;

    float *p_t, *p_tn, *p_q, *p_k, *p_v, *p_ao, *p_attn, *p_ffh, *p_stats;
    cudaGetSymbolAddress((void**)&p_t,    g_t);
    cudaGetSymbolAddress((void**)&p_tn,   g_tn);
    cudaGetSymbolAddress((void**)&p_q,    g_q);
    cudaGetSymbolAddress((void**)&p_k,    g_k);
    cudaGetSymbolAddress((void**)&p_v,    g_v);
    cudaGetSymbolAddress((void**)&p_ao,   g_ao);
    cudaGetSymbolAddress((void**)&p_attn, g_attn);
    cudaGetSymbolAddress((void**)&p_ffh,  g_ffh);
    cudaGetSymbolAddress((void**)&p_stats,g_stats);

    const long NEL = (long)BB * CC * SS;   // 4,194,304

    // stage 0: groupnorm (+transpose to (b,s,c)) then proj_in
    gn_stats_k<<<BB * 32, 256>>>(x, p_stats);
    gn_apply_k<<<(int)((NEL + 255) / 256), 256>>>(x, p_stats, gn_s, gn_b, p_tn);
    gemm_big(p_tn, pin_w, pin_b, nullptr, p_t, MM, CC, CC, CC, CC, CC);

    for (int l = 0; l < 2; l++){
        const float* wq = sa_wq + (long)l * CC * CC;
        const float* wk = sa_wk + (long)l * CC * CC;
        const float* wv = sa_wv + (long)l * CC * CC;
        const float* wo = sa_wo + (long)l * CC * CC;
        const float* bo = sa_bo + (long)l * CC;
        const float* cwq = ca_wq + (long)l * CC * CC;
        const float* cwk = ca_wk + (long)l * DCC * CC;
        const float* cwv = ca_wv + (long)l * DCC * CC;
        const float* cwo = ca_wo + (long)l * CC * CC;
        const float* cbo = ca_bo + (long)l * CC;
        const float* w1 = ff_w1 + (long)l * CC * 4096;
        const float* b1 = ff_b1 + (long)l * 4096;
        const float* w2 = ff_w2 + (long)l * 2048 * CC;
        const float* b2 = ff_b2 + (long)l * CC;

        // ---- self-attention ----
        layernorm_k<<<MM, 128>>>(p_t, ln1_s + l * CC, ln1_b + l * CC, p_tn);
        gemm_big(p_tn, wq, nullptr, nullptr, p_q, MM, CC, CC, CC, CC, CC);
        gemm_big(p_tn, wk, nullptr, nullptr, p_k, MM, CC, CC, CC, CC, CC);
        gemm_big(p_tn, wv, nullptr, nullptr, p_v, MM, CC, CC, CC, CC, CC);
        {   // QK^T per (b,h): M=1024 N=1024 K=64, NT
            dim3 g(1024 / 128, 1024 / 128, BB * NHH);
            gemm_k<128,128,8,true><<<g, 256>>>(p_q, p_k, nullptr, nullptr, p_attn,
                1024, 1024, 64, CC, CC, 1024,
                NHH, (long)SS * CC, DHH, (long)SS * CC, DHH,
                (long)NHH * SS * SS, (long)SS * SS);
        }
        softmax_k<32><<<(BB * NHH * SS + 7) / 8, 256>>>(p_attn, (long)BB * NHH * SS, 1024, 1024);
        {   // attn @ V per (b,h): M=1024 N=64 K=1024, NN
            dim3 g(1, 1024 / 128, BB * NHH);
            gemm_k<128,64,8,false><<<g, 128>>>(p_attn, p_v, nullptr, nullptr, p_ao,
                1024, 64, 1024, 1024, CC, CC,
                NHH, (long)NHH * SS * SS, (long)SS * SS,
                (long)SS * CC, DHH, (long)SS * CC, DHH);
        }
        gemm_big(p_ao, wo, bo, p_t, p_t, MM, CC, CC, CC, CC, CC); // +residual

        // ---- cross-attention ----
        layernorm_k<<<MM, 128>>>(p_t, ln2_s + l * CC, ln2_b + l * CC, p_tn);
        gemm_big(p_tn, cwq, nullptr, nullptr, p_q, MM, CC, CC, CC, CC, CC);
        gemm_big(cond, cwk, nullptr, nullptr, p_k, BB * NCC, CC, DCC, DCC, CC, CC);
        gemm_big(cond, cwv, nullptr, nullptr, p_v, BB * NCC, CC, DCC, DCC, CC, CC);
        {   // QK^T: M=1024 N=77 K=64, scores ld=80
            dim3 g((NCC + 63) / 64, 1024 / 128, BB * NHH);
            gemm_k<128,64,8,true><<<g, 128>>>(p_q, p_k, nullptr, nullptr, p_attn,
                1024, NCC, 64, CC, CC, 80,
                NHH, (long)SS * CC, DHH, (long)NCC * CC, DHH,
                (long)NHH * SS * 80, (long)SS * 80);
        }
        softmax_k<3><<<(BB * NHH * SS + 7) / 8, 256>>>(p_attn, (long)BB * NHH * SS, NCC, 80);
        {   // attn @ V: M=1024 N=64 K=77
            dim3 g(1, 1024 / 128, BB * NHH);
            gemm_k<128,64,8,false><<<g, 128>>>(p_attn, p_v, nullptr, nullptr, p_ao,
                1024, 64, NCC, 80, CC, CC,
                NHH, (long)NHH * SS * 80, (long)SS * 80,
                (long)NCC * CC, DHH, (long)SS * CC, DHH);
        }
        gemm_big(p_ao, cwo, cbo, p_t, p_t, MM, CC, CC, CC, CC, CC); // +residual

        // ---- FFN (GEGLU) ----
        layernorm_k<<<MM, 128>>>(p_t, ln3_s + l * CC, ln3_b + l * CC, p_tn);
        gemm_big(p_tn, w1, b1, nullptr, p_ffh, MM, 4096, CC, CC, 4096, 4096);
        geglu_k<<<(int)(((long)MM * 2048 + 255) / 256), 256>>>(p_ffh, p_attn);
        gemm_big(p_attn, w2, b2, p_t, p_t, MM, CC, 2048, 2048, CC, CC); // +residual
    }

    // final: proj_out, transpose back, + x_in skip
    gemm_big(p_t, pout_w, pout_b, nullptr, p_tn, MM, CC, CC, CC, CC, CC);
    out_add_k<<<(int)((NEL + 255) / 256), 256>>>(p_tn, x, out);
}

// round 2
// speedup vs baseline: 1.6381x; 1.6381x over previous
#include <cuda_runtime.h>
#include <math.h>
#include <stdint.h>

// ---------------- problem constants ----------------
constexpr int BB   = 8;        // batch
constexpr int CC   = 512;      // channels
constexpr int SS   = 1024;     // H*W sequence length
constexpr int NHH  = 8;        // heads
constexpr int DHH  = 64;       // head dim
constexpr int NCC  = 77;       // cond tokens
constexpr int DCC  = 768;      // cond dim
constexpr int MM   = BB * SS;  // 8192 rows

// ---------------- scratch (__device__ globals, no allocs) ----------------
__device__ float g_t   [ (long)MM * CC ];
__device__ float g_tn  [ (long)MM * CC ];
__device__ float g_q   [ (long)MM * CC ];
__device__ float g_k   [ (long)MM * CC ];
__device__ float g_v   [ (long)MM * CC ];
__device__ float g_ao  [ (long)MM * CC ];
__device__ float g_attn[ 64L * 1024 * 1024 ];      // scores / GEGLU scratch
__device__ float g_ffh [ (long)MM * 4096 ];        // FFN hidden
__device__ float g_stats[ 2 * BB * 32 ];

// ---------------- reductions ----------------
__inline__ __device__ float warpSum(float v){
    #pragma unroll
    for (int o = 16; o > 0; o >>= 1) v += __shfl_xor_sync(0xffffffffu, v, o);
    return v;
}
__inline__ __device__ float warpMax(float v){
    #pragma unroll
    for (int o = 16; o > 0; o >>= 1) v = fmaxf(v, __shfl_xor_sync(0xffffffffu, v, o));
    return v;
}

__inline__ __device__ uint32_t f2tf32(float f){
    uint32_t u;
    asm("cvt.rna.tf32.f32 %0, %1;" : "=r"(u) : "f"(f));
    return u;
}

// ---------------- groupnorm ----------------
__global__ void gn_stats_k(const float* __restrict__ x, float* __restrict__ stats){
    long base = (long)blockIdx.x * 16384;
    float s = 0.f, q = 0.f;
    for (int i = threadIdx.x; i < 16384; i += blockDim.x){
        float v = x[base + i];
        s += v; q += v * v;
    }
    __shared__ float shs[8], shq[8];
    s = warpSum(s); q = warpSum(q);
    int w = threadIdx.x >> 5, l = threadIdx.x & 31;
    if (l == 0){ shs[w] = s; shq[w] = q; }
    __syncthreads();
    if (threadIdx.x < 32){
        s = (l < 8) ? shs[l] : 0.f;
        q = (l < 8) ? shq[l] : 0.f;
        s = warpSum(s); q = warpSum(q);
        if (l == 0){
            float mean = s * (1.f / 16384.f);
            float var  = q * (1.f / 16384.f) - mean * mean;
            stats[2 * blockIdx.x]     = mean;
            stats[2 * blockIdx.x + 1] = rsqrtf(var + 1e-6f);
        }
    }
}

__global__ void gn_apply_k(const float* __restrict__ x, const float* __restrict__ stats,
                           const float* __restrict__ gs, const float* __restrict__ gb,
                           float* __restrict__ out){
    long idx = (long)blockIdx.x * blockDim.x + threadIdx.x;
    if (idx >= (long)BB * CC * SS) return;
    int p = (int)(idx & 1023);
    int c = (int)((idx >> 10) & 511);
    int b = (int)(idx >> 19);
    int grp = b * 32 + (c >> 4);
    float mean = stats[2 * grp], rstd = stats[2 * grp + 1];
    float v = (x[idx] - mean) * rstd * gs[c] + gb[c];
    out[(((long)b << 10) + p) * CC + c] = v;
}

// ---------------- layernorm ----------------
__global__ void layernorm_k(const float* __restrict__ in, const float* __restrict__ sc,
                            const float* __restrict__ bi, float* __restrict__ out){
    long row = blockIdx.x;
    const float4* x4 = (const float4*)(in + row * CC);
    float4 xv = x4[threadIdx.x];
    float s = xv.x + xv.y + xv.z + xv.w;
    float q = xv.x*xv.x + xv.y*xv.y + xv.z*xv.z + xv.w*xv.w;
    __shared__ float shs[4], shq[4];
    s = warpSum(s); q = warpSum(q);
    int w = threadIdx.x >> 5, l = threadIdx.x & 31;
    if (l == 0){ shs[w] = s; shq[w] = q; }
    __syncthreads();
    if (threadIdx.x < 32){
        float a = (l < 4) ? shs[l] : 0.f;
        float b2 = (l < 4) ? shq[l] : 0.f;
        a = warpSum(a); b2 = warpSum(b2);
        if (l == 0){ shs[0] = a; shq[0] = b2; }
    }
    __syncthreads();
    float mean = shs[0] * (1.f / 512.f);
    float rstd = rsqrtf(shq[0] * (1.f / 512.f) - mean * mean + 1e-5f);
    float4 sv = ((const float4*)sc)[threadIdx.x];
    float4 bv = ((const float4*)bi)[threadIdx.x];
    float4 o;
    o.x = (xv.x - mean) * rstd * sv.x + bv.x;
    o.y = (xv.y - mean) * rstd * sv.y + bv.y;
    o.z = (xv.z - mean) * rstd * sv.z + bv.z;
    o.w = (xv.w - mean) * rstd * sv.w + bv.w;
    ((float4*)(out + row * CC))[threadIdx.x] = o;
}

// ---------------- softmax ----------------
template<int NJ>
__global__ void softmax_k(float* __restrict__ p, long nrows, int ncols, int ld){
    long row = (long)blockIdx.x * (blockDim.x >> 5) + (threadIdx.x >> 5);
    if (row >= nrows) return;
    int lane = threadIdx.x & 31;
    float* r = p + row * (long)ld;
    float xs[NJ];
    float mx = -1e30f;
    #pragma unroll
    for (int t = 0; t < NJ; t++){
        int j = lane + t * 32;
        xs[t] = (j < ncols) ? r[j] : -1e30f;
        mx = fmaxf(mx, xs[t]);
    }
    mx = warpMax(mx);
    float sum = 0.f;
    #pragma unroll
    for (int t = 0; t < NJ; t++){ xs[t] = __expf(xs[t] - mx); sum += xs[t]; }
    sum = warpSum(sum);
    float inv = 1.f / sum;
    #pragma unroll
    for (int t = 0; t < NJ; t++){
        int j = lane + t * 32;
        if (j < ncols)      r[j] = xs[t] * inv;
        else if (j < ld)    r[j] = 0.f;
    }
}

// ---------------- GEGLU ----------------
__global__ void geglu_k(const float* __restrict__ h, float* __restrict__ g){
    long idx = (long)blockIdx.x * blockDim.x + threadIdx.x;
    if (idx >= (long)MM * 2048) return;
    long m = idx >> 11;
    int  i = (int)(idx & 2047);
    float u    = h[m * 4096 + i];
    float gate = h[m * 4096 + 2048 + i];
    float ge = 0.5f * gate * (1.f + erff(gate * 0.70710678118654752f));
    g[idx] = u * ge;
}

// ---------------- final: transpose-back + x_in residual ----------------
__global__ void out_add_k(const float* __restrict__ z, const float* __restrict__ x,
                          float* __restrict__ out){
    long idx = (long)blockIdx.x * blockDim.x + threadIdx.x;
    if (idx >= (long)BB * CC * SS) return;
    int p = (int)(idx & 1023);
    int d = (int)((idx >> 10) & 511);
    long b = idx >> 19;
    out[idx] = z[((b << 10) + p) * CC + d] + x[idx];
}

// =====================================================================
// tf32 tensor-core GEMM via mma.sync.m16n8k8
// C[m,n] = sum_k A[m,k] * (TB ? B[n,k] : B[k,n]) (+bias[n]) (+res[m,n])
// Warp tile 64x32 (4x4 m16n8k8 tiles). Double-buffered smem with
// register staging. fp32 -> tf32 (cvt.rna) at smem store.
// =====================================================================
__inline__ __device__ void mma_tf32(float* c, const uint32_t* a, const uint32_t* b){
    asm volatile(
        "mma.sync.aligned.m16n8k8.row.col.f32.tf32.tf32.f32 "
        "{%0,%1,%2,%3}, {%4,%5,%6,%7}, {%8,%9}, {%0,%1,%2,%3};"
        : "+f"(c[0]), "+f"(c[1]), "+f"(c[2]), "+f"(c[3])
        : "r"(a[0]), "r"(a[1]), "r"(a[2]), "r"(a[3]), "r"(b[0]), "r"(b[1]));
}

template<int BM, int BN, int BK, bool TB>
__global__ void mma_gemm_k(const float* __restrict__ A, const float* __restrict__ Bm,
                           const float* __restrict__ bias, const float* __restrict__ res,
                           float* __restrict__ C,
                           int M, int N, int K, int lda, int ldb, int ldc,
                           int bdiv, long sAo, long sAi, long sBo, long sBi, long sCo, long sCi){
    constexpr int WM = 64, WN = 32;
    constexpr int WARPS_M = BM / WM, WARPS_N = BN / WN;
    constexpr int THREADS = WARPS_M * WARPS_N * 32;
    constexpr int LA = BM * BK / THREADS;
    constexpr int LB = BN * BK / THREADS;

    __shared__ uint32_t As[2][BK][BM + 4];
    __shared__ uint32_t Bs[2][BK][BN + 4];

    int z = blockIdx.z;
    long aoff = (long)(z / bdiv) * sAo + (long)(z % bdiv) * sAi;
    long boff = (long)(z / bdiv) * sBo + (long)(z % bdiv) * sBi;
    long coff = (long)(z / bdiv) * sCo + (long)(z % bdiv) * sCi;
    A += aoff; Bm += boff; C += coff;
    if (res) res += coff;

    int tid  = threadIdx.x;
    int warp = tid >> 5, lane = tid & 31;
    int g  = lane >> 2;     // group id (0..7)
    int tg = lane & 3;      // thread in group (0..3)
    int wm = (warp % WARPS_M) * WM;
    int wn = (warp / WARPS_M) * WN;
    int row0 = blockIdx.y * BM;
    int col0 = blockIdx.x * BN;

    float acc[4][4][4];
    #pragma unroll
    for (int i = 0; i < 4; i++)
        #pragma unroll
        for (int j = 0; j < 4; j++)
            #pragma unroll
            for (int r = 0; r < 4; r++) acc[i][j][r] = 0.f;

    float regA[LA], regB[LB];

    auto loadA = [&](int kt){
        #pragma unroll
        for (int it = 0; it < LA; it++){
            int idx = tid + it * THREADS;
            int i = idx / BK, j = idx % BK;
            int m = row0 + i, k = kt + j;
            regA[it] = (m < M && k < K) ? A[(long)m * lda + k] : 0.f;
        }
    };
    auto loadB = [&](int kt){
        #pragma unroll
        for (int it = 0; it < LB; it++){
            int idx = tid + it * THREADS;
            if (TB){
                int j = idx % BK, i = idx / BK;
                int n = col0 + i, k = kt + j;
                regB[it] = (n < N && k < K) ? Bm[(long)n * ldb + k] : 0.f;
            } else {
                int i = idx % BN, j = idx / BN;
                int n = col0 + i, k = kt + j;
                regB[it] = (n < N && k < K) ? Bm[(long)k * ldb + n] : 0.f;
            }
        }
    };
    auto stage = [&](int buf){
        #pragma unroll
        for (int it = 0; it < LA; it++){
            int idx = tid + it * THREADS;
            int i = idx / BK, j = idx % BK;
            As[buf][j][i] = f2tf32(regA[it]);
        }
        #pragma unroll
        for (int it = 0; it < LB; it++){
            int idx = tid + it * THREADS;
            int i, j;
            if (TB){ j = idx % BK; i = idx / BK; }
            else   { i = idx % BN; j = idx / BN; }
            Bs[buf][j][i] = f2tf32(regB[it]);
        }
    };
    auto compute = [&](int buf){
        #pragma unroll
        for (int ks = 0; ks < BK; ks += 8){
            uint32_t bf[4][2];
            #pragma unroll
            for (int j = 0; j < 4; j++){
                bf[j][0] = Bs[buf][ks + tg    ][wn + j * 8 + g];
                bf[j][1] = Bs[buf][ks + tg + 4][wn + j * 8 + g];
            }
            #pragma unroll
            for (int i = 0; i < 4; i++){
                uint32_t af[4];
                int mr = wm + i * 16 + g;
                af[0] = As[buf][ks + tg    ][mr    ];
                af[1] = As[buf][ks + tg    ][mr + 8];
                af[2] = As[buf][ks + tg + 4][mr    ];
                af[3] = As[buf][ks + tg + 4][mr + 8];
                #pragma unroll
                for (int j = 0; j < 4; j++)
                    mma_tf32(acc[i][j], af, bf[j]);
            }
        }
    };

    int nk = (K + BK - 1) / BK;
    loadA(0); loadB(0);
    stage(0);
    __syncthreads();

    for (int t = 0; t < nk; t++){
        if (t + 1 < nk){ loadA((t + 1) * BK); loadB((t + 1) * BK); }
        compute(t & 1);
        if (t + 1 < nk) stage((t + 1) & 1);
        __syncthreads();
    }

    // epilogue
    #pragma unroll
    for (int i = 0; i < 4; i++){
        int r0 = row0 + wm + i * 16 + g;
        int r1 = r0 + 8;
        #pragma unroll
        for (int j = 0; j < 4; j++){
            int c0 = col0 + wn + j * 8 + 2 * tg;
            float* a4 = acc[i][j];
            if (r0 < M){
                if (c0 < N){
                    float v = a4[0];
                    if (bias) v += bias[c0];
                    if (res)  v += res[(long)r0 * ldc + c0];
                    C[(long)r0 * ldc + c0] = v;
                }
                if (c0 + 1 < N){
                    float v = a4[1];
                    if (bias) v += bias[c0 + 1];
                    if (res)  v += res[(long)r0 * ldc + c0 + 1];
                    C[(long)r0 * ldc + c0 + 1] = v;
                }
            }
            if (r1 < M){
                if (c0 < N){
                    float v = a4[2];
                    if (bias) v += bias[c0];
                    if (res)  v += res[(long)r1 * ldc + c0];
                    C[(long)r1 * ldc + c0] = v;
                }
                if (c0 + 1 < N){
                    float v = a4[3];
                    if (bias) v += bias[c0 + 1];
                    if (res)  v += res[(long)r1 * ldc + c0 + 1];
                    C[(long)r1 * ldc + c0 + 1] = v;
                }
            }
        }
    }
}

// ---------------- host-side helpers ----------------
static void gemm_big(const float* A, const float* W, const float* bias, const float* res,
                     float* C, int M, int N, int K, int lda, int ldb, int ldc){
    dim3 g((N + 127) / 128, (M + 127) / 128, 1);
    mma_gemm_k<128,128,16,false><<<g, 256>>>(A, W, bias, res, C, M, N, K, lda, ldb, ldc,
                                             1, 0, 0, 0, 0, 0, 0);
}

extern "C" void kernel_launch(void* const* d_in, const int* in_sizes, int n_in,
                              void* d_out, int out_size){
    (void)in_sizes; (void)n_in; (void)out_size;
    const float* x      = (const float*)d_in[0];
    const float* cond   = (const float*)d_in[1];
    const float* gn_s   = (const float*)d_in[2];
    const float* gn_b   = (const float*)d_in[3];
    const float* pin_w  = (const float*)d_in[4];
    const float* pin_b  = (const float*)d_in[5];
    const float* pout_w = (const float*)d_in[6];
    const float* pout_b = (const float*)d_in[7];
    const float* ln1_s  = (const float*)d_in[8];
    const float* ln1_b  = (const float*)d_in[9];
    const float* sa_wq  = (const float*)d_in[10];
    const float* sa_wk  = (const float*)d_in[11];
    const float* sa_wv  = (const float*)d_in[12];
    const float* sa_wo  = (const float*)d_in[13];
    const float* sa_bo  = (const float*)d_in[14];
    const float* ln2_s  = (const float*)d_in[15];
    const float* ln2_b  = (const float*)d_in[16];
    const float* ca_wq  = (const float*)d_in[17];
    const float* ca_wk  = (const float*)d_in[18];
    const float* ca_wv  = (const float*)d_in[19];
    const float* ca_wo  = (const float*)d_in[20];
    const float* ca_bo  = (const float*)d_in[21];
    const float* ln3_s  = (const float*)d_in[22];
    const float* ln3_b  = (const float*)d_in[23];
    const float* ff_w1  = (const float*)d_in[24];
    const float* ff_b1  = (const float*)d_in[25];
    const float* ff_w2  = (const float*)d_in[26];
    const float* ff_b2  = (const float*)d_in[27];
    float* out = (float*)d_out;

    float *p_t, *p_tn, *p_q, *p_k, *p_v, *p_ao, *p_attn, *p_ffh, *p_stats;
    cudaGetSymbolAddress((void**)&p_t,    g_t);
    cudaGetSymbolAddress((void**)&p_tn,   g_tn);
    cudaGetSymbolAddress((void**)&p_q,    g_q);
    cudaGetSymbolAddress((void**)&p_k,    g_k);
    cudaGetSymbolAddress((void**)&p_v,    g_v);
    cudaGetSymbolAddress((void**)&p_ao,   g_ao);
    cudaGetSymbolAddress((void**)&p_attn, g_attn);
    cudaGetSymbolAddress((void**)&p_ffh,  g_ffh);
    cudaGetSymbolAddress((void**)&p_stats,g_stats);

    const long NEL = (long)BB * CC * SS;

    gn_stats_k<<<BB * 32, 256>>>(x, p_stats);
    gn_apply_k<<<(int)((NEL + 255) / 256), 256>>>(x, p_stats, gn_s, gn_b, p_tn);
    gemm_big(p_tn, pin_w, pin_b, nullptr, p_t, MM, CC, CC, CC, CC, CC);

    for (int l = 0; l < 2; l++){
        const float* wq = sa_wq + (long)l * CC * CC;
        const float* wk = sa_wk + (long)l * CC * CC;
        const float* wv = sa_wv + (long)l * CC * CC;
        const float* wo = sa_wo + (long)l * CC * CC;
        const float* bo = sa_bo + (long)l * CC;
        const float* cwq = ca_wq + (long)l * CC * CC;
        const float* cwk = ca_wk + (long)l * DCC * CC;
        const float* cwv = ca_wv + (long)l * DCC * CC;
        const float* cwo = ca_wo + (long)l * CC * CC;
        const float* cbo = ca_bo + (long)l * CC;
        const float* w1 = ff_w1 + (long)l * CC * 4096;
        const float* b1 = ff_b1 + (long)l * 4096;
        const float* w2 = ff_w2 + (long)l * 2048 * CC;
        const float* b2 = ff_b2 + (long)l * CC;

        // ---- self-attention ----
        layernorm_k<<<MM, 128>>>(p_t, ln1_s + l * CC, ln1_b + l * CC, p_tn);
        gemm_big(p_tn, wq, nullptr, nullptr, p_q, MM, CC, CC, CC, CC, CC);
        gemm_big(p_tn, wk, nullptr, nullptr, p_k, MM, CC, CC, CC, CC, CC);
        gemm_big(p_tn, wv, nullptr, nullptr, p_v, MM, CC, CC, CC, CC, CC);
        {   // QK^T per (b,h): M=1024 N=1024 K=64, NT
            dim3 g(1024 / 128, 1024 / 128, BB * NHH);
            mma_gemm_k<128,128,16,true><<<g, 256>>>(p_q, p_k, nullptr, nullptr, p_attn,
                1024, 1024, 64, CC, CC, 1024,
                NHH, (long)SS * CC, DHH, (long)SS * CC, DHH,
                (long)NHH * SS * SS, (long)SS * SS);
        }
        softmax_k<32><<<(BB * NHH * SS + 7) / 8, 256>>>(p_attn, (long)BB * NHH * SS, 1024, 1024);
        {   // attn @ V per (b,h): M=1024 N=64 K=1024, NN
            dim3 g(1, 1024 / 128, BB * NHH);
            mma_gemm_k<128,64,16,false><<<g, 128>>>(p_attn, p_v, nullptr, nullptr, p_ao,
                1024, 64, 1024, 1024, CC, CC,
                NHH, (long)NHH * SS * SS, (long)SS * SS,
                (long)SS * CC, DHH, (long)SS * CC, DHH);
        }
        gemm_big(p_ao, wo, bo, p_t, p_t, MM, CC, CC, CC, CC, CC); // +residual

        // ---- cross-attention ----
        layernorm_k<<<MM, 128>>>(p_t, ln2_s + l * CC, ln2_b + l * CC, p_tn);
        gemm_big(p_tn, cwq, nullptr, nullptr, p_q, MM, CC, CC, CC, CC, CC);
        gemm_big(cond, cwk, nullptr, nullptr, p_k, BB * NCC, CC, DCC, DCC, CC, CC);
        gemm_big(cond, cwv, nullptr, nullptr, p_v, BB * NCC, CC, DCC, DCC, CC, CC);
        {   // QK^T: M=1024 N=77 K=64, scores ld=80
            dim3 g(1, 1024 / 128, BB * NHH);
            mma_gemm_k<128,128,16,true><<<g, 256>>>(p_q, p_k, nullptr, nullptr, p_attn,
                1024, NCC, 64, CC, CC, 80,
                NHH, (long)SS * CC, DHH, (long)NCC * CC, DHH,
                (long)NHH * SS * 80, (long)SS * 80);
        }
        softmax_k<3><<<(BB * NHH * SS + 7) / 8, 256>>>(p_attn, (long)BB * NHH * SS, NCC, 80);
        {   // attn @ V: M=1024 N=64 K=77
            dim3 g(1, 1024 / 128, BB * NHH);
            mma_gemm_k<128,64,16,false><<<g, 128>>>(p_attn, p_v, nullptr, nullptr, p_ao,
                1024, 64, NCC, 80, CC, CC,
                NHH, (long)NHH * SS * 80, (long)SS * 80,
                (long)NCC * CC, DHH, (long)SS * CC, DHH);
        }
        gemm_big(p_ao, cwo, cbo, p_t, p_t, MM, CC, CC, CC, CC, CC); // +residual

        // ---- FFN (GEGLU) ----
        layernorm_k<<<MM, 128>>>(p_t, ln3_s + l * CC, ln3_b + l * CC, p_tn);
        gemm_big(p_tn, w1, b1, nullptr, p_ffh, MM, 4096, CC, CC, 4096, 4096);
        geglu_k<<<(int)(((long)MM * 2048 + 255) / 256), 256>>>(p_ffh, p_attn);
        gemm_big(p_attn, w2, b2, p_t, p_t, MM, CC, 2048, 2048, CC, CC); // +residual
    }

    gemm_big(p_t, pout_w, pout_b, nullptr, p_tn, MM, CC, CC, CC, CC, CC);
    out_add_k<<<(int)((NEL + 255) / 256), 256>>>(p_tn, x, out);
}

// round 4
// speedup vs baseline: 3.3458x; 2.0425x over previous
#include <cuda_runtime.h>
#include <math.h>
#include <stdint.h>

// ---------------- problem constants ----------------
constexpr int BB   = 8;
constexpr int CC   = 512;
constexpr int SS   = 1024;
constexpr int NHH  = 8;
constexpr int DHH  = 64;
constexpr int NCC  = 77;
constexpr int DCC  = 768;
constexpr int MM   = BB * SS;  // 8192

// ---------------- scratch ----------------
__device__ __align__(256) float g_t   [ (long)MM * CC ];
__device__ __align__(256) float g_tn  [ (long)MM * CC ];
__device__ __align__(256) float g_q   [ (long)MM * CC ];
__device__ __align__(256) float g_k   [ (long)MM * CC ];
__device__ __align__(256) float g_v   [ (long)MM * CC ];
__device__ __align__(256) float g_ao  [ (long)MM * CC ];
__device__ __align__(256) float g_attn[ 64L * 1024 * 1024 ];
__device__ __align__(256) float g_ffh [ (long)MM * 4096 ];
__device__ __align__(256) float g_stats[ 2 * BB * 32 ];

// ---------------- reductions ----------------
__inline__ __device__ float warpSum(float v){
    #pragma unroll
    for (int o = 16; o > 0; o >>= 1) v += __shfl_xor_sync(0xffffffffu, v, o);
    return v;
}
__inline__ __device__ float warpMax(float v){
    #pragma unroll
    for (int o = 16; o > 0; o >>= 1) v = fmaxf(v, __shfl_xor_sync(0xffffffffu, v, o));
    return v;
}

// ---------------- cp.async helpers ----------------
__device__ __forceinline__ uint32_t smem_u32(const void* p){
    return (uint32_t)__cvta_generic_to_shared(p);
}
__device__ __forceinline__ void cp16(void* dst, const void* src, int bytes){
    asm volatile("cp.async.cg.shared.global [%0], [%1], 16, %2;\n"
                 :: "r"(smem_u32(dst)), "l"(src), "r"(bytes));
}
__device__ __forceinline__ void cp_commit(){ asm volatile("cp.async.commit_group;\n"); }
template<int N> __device__ __forceinline__ void cp_wait(){
    asm volatile("cp.async.wait_group %0;\n" :: "n"(N));
}

// ---------------- groupnorm stats ----------------
__global__ void gn_stats_k(const float* __restrict__ x, float* __restrict__ stats){
    long base = (long)blockIdx.x * 16384;
    float s = 0.f, q = 0.f;
    for (int i = threadIdx.x; i < 16384; i += blockDim.x){
        float v = x[base + i];
        s += v; q += v * v;
    }
    __shared__ float shs[8], shq[8];
    s = warpSum(s); q = warpSum(q);
    int w = threadIdx.x >> 5, l = threadIdx.x & 31;
    if (l == 0){ shs[w] = s; shq[w] = q; }
    __syncthreads();
    if (threadIdx.x < 32){
        s = (l < 8) ? shs[l] : 0.f;
        q = (l < 8) ? shq[l] : 0.f;
        s = warpSum(s); q = warpSum(q);
        if (l == 0){
            float mean = s * (1.f / 16384.f);
            float var  = q * (1.f / 16384.f) - mean * mean;
            stats[2 * blockIdx.x]     = mean;
            stats[2 * blockIdx.x + 1] = rsqrtf(var + 1e-6f);
        }
    }
}

// ---------------- groupnorm apply + transpose (tiled) ----------------
__global__ void gn_apply_t_k(const float* __restrict__ x, const float* __restrict__ stats,
                             const float* __restrict__ gs, const float* __restrict__ gb,
                             float* __restrict__ out){
    __shared__ float tile[32][33];
    int b = blockIdx.z, c0 = blockIdx.y * 32, p0 = blockIdx.x * 32;
    int tx = threadIdx.x, ty = threadIdx.y;
    #pragma unroll
    for (int r = 0; r < 4; r++){
        int c = c0 + ty + r * 8;
        float v = x[((long)b * CC + c) * SS + p0 + tx];
        int grp = b * 32 + (c >> 4);
        v = (v - stats[2 * grp]) * stats[2 * grp + 1] * gs[c] + gb[c];
        tile[ty + r * 8][tx] = v;
    }
    __syncthreads();
    #pragma unroll
    for (int r = 0; r < 4; r++){
        int p = p0 + ty + r * 8;
        out[((long)b * SS + p) * CC + c0 + tx] = tile[tx][ty + r * 8];
    }
}

// ---------------- final transpose + x_in residual (tiled) ----------------
__global__ void out_add_t_k(const float* __restrict__ z, const float* __restrict__ x,
                            float* __restrict__ out){
    __shared__ float tile[32][33];
    int b = blockIdx.z, c0 = blockIdx.y * 32, p0 = blockIdx.x * 32;
    int tx = threadIdx.x, ty = threadIdx.y;
    #pragma unroll
    for (int r = 0; r < 4; r++){
        int p = p0 + ty + r * 8;
        tile[ty + r * 8][tx] = z[((long)b * SS + p) * CC + c0 + tx];
    }
    __syncthreads();
    #pragma unroll
    for (int r = 0; r < 4; r++){
        int c = c0 + ty + r * 8;
        long o = ((long)b * CC + c) * SS + p0 + tx;
        out[o] = tile[tx][ty + r * 8] + x[o];
    }
}

// ---------------- layernorm ----------------
__global__ void layernorm_k(const float* __restrict__ in, const float* __restrict__ sc,
                            const float* __restrict__ bi, float* __restrict__ out){
    long row = blockIdx.x;
    const float4* x4 = (const float4*)(in + row * CC);
    float4 xv = x4[threadIdx.x];
    float s = xv.x + xv.y + xv.z + xv.w;
    float q = xv.x*xv.x + xv.y*xv.y + xv.z*xv.z + xv.w*xv.w;
    __shared__ float shs[4], shq[4];
    s = warpSum(s); q = warpSum(q);
    int w = threadIdx.x >> 5, l = threadIdx.x & 31;
    if (l == 0){ shs[w] = s; shq[w] = q; }
    __syncthreads();
    if (threadIdx.x < 32){
        float a = (l < 4) ? shs[l] : 0.f;
        float b2 = (l < 4) ? shq[l] : 0.f;
        a = warpSum(a); b2 = warpSum(b2);
        if (l == 0){ shs[0] = a; shq[0] = b2; }
    }
    __syncthreads();
    float mean = shs[0] * (1.f / 512.f);
    float rstd = rsqrtf(shq[0] * (1.f / 512.f) - mean * mean + 1e-5f);
    float4 sv = ((const float4*)sc)[threadIdx.x];
    float4 bv = ((const float4*)bi)[threadIdx.x];
    float4 o;
    o.x = (xv.x - mean) * rstd * sv.x + bv.x;
    o.y = (xv.y - mean) * rstd * sv.y + bv.y;
    o.z = (xv.z - mean) * rstd * sv.z + bv.z;
    o.w = (xv.w - mean) * rstd * sv.w + bv.w;
    ((float4*)(out + row * CC))[threadIdx.x] = o;
}

// ---------------- softmax (vectorized) ----------------
template<int NJ4>
__global__ void softmax4_k(float* __restrict__ p, long nrows){
    long row = (long)blockIdx.x * (blockDim.x >> 5) + (threadIdx.x >> 5);
    if (row >= nrows) return;
    int lane = threadIdx.x & 31;
    float4* r = (float4*)(p + row * (long)(NJ4 * 128));
    float4 xs[NJ4];
    float mx = -1e30f;
    #pragma unroll
    for (int t = 0; t < NJ4; t++){
        xs[t] = r[lane + t * 32];
        mx = fmaxf(mx, fmaxf(fmaxf(xs[t].x, xs[t].y), fmaxf(xs[t].z, xs[t].w)));
    }
    mx = warpMax(mx);
    float sum = 0.f;
    #pragma unroll
    for (int t = 0; t < NJ4; t++){
        xs[t].x = __expf(xs[t].x - mx); xs[t].y = __expf(xs[t].y - mx);
        xs[t].z = __expf(xs[t].z - mx); xs[t].w = __expf(xs[t].w - mx);
        sum += xs[t].x + xs[t].y + xs[t].z + xs[t].w;
    }
    sum = warpSum(sum);
    float inv = 1.f / sum;
    #pragma unroll
    for (int t = 0; t < NJ4; t++){
        xs[t].x *= inv; xs[t].y *= inv; xs[t].z *= inv; xs[t].w *= inv;
        r[lane + t * 32] = xs[t];
    }
}

// scalar softmax for ragged (cross-attn) rows
template<int NJ>
__global__ void softmax_k(float* __restrict__ p, long nrows, int ncols, int ld){
    long row = (long)blockIdx.x * (blockDim.x >> 5) + (threadIdx.x >> 5);
    if (row >= nrows) return;
    int lane = threadIdx.x & 31;
    float* r = p + row * (long)ld;
    float xs[NJ];
    float mx = -1e30f;
    #pragma unroll
    for (int t = 0; t < NJ; t++){
        int j = lane + t * 32;
        xs[t] = (j < ncols) ? r[j] : -1e30f;
        mx = fmaxf(mx, xs[t]);
    }
    mx = warpMax(mx);
    float sum = 0.f;
    #pragma unroll
    for (int t = 0; t < NJ; t++){ xs[t] = __expf(xs[t] - mx); sum += xs[t]; }
    sum = warpSum(sum);
    float inv = 1.f / sum;
    #pragma unroll
    for (int t = 0; t < NJ; t++){
        int j = lane + t * 32;
        if (j < ncols)      r[j] = xs[t] * inv;
        else if (j < ld)    r[j] = 0.f;
    }
}

// ---------------- GEGLU (float4) ----------------
__global__ void geglu4_k(const float* __restrict__ h, float* __restrict__ g){
    long idx = (long)blockIdx.x * blockDim.x + threadIdx.x;
    if (idx >= (long)MM * 512) return;
    long m = idx >> 9;
    int  i = (int)(idx & 511);
    const float4* h4 = (const float4*)h;
    float4 u    = h4[m * 1024 + i];
    float4 gate = h4[m * 1024 + 512 + i];
    float4 o;
    o.x = u.x * (0.5f * gate.x * (1.f + erff(gate.x * 0.70710678118654752f)));
    o.y = u.y * (0.5f * gate.y * (1.f + erff(gate.y * 0.70710678118654752f)));
    o.z = u.z * (0.5f * gate.z * (1.f + erff(gate.z * 0.70710678118654752f)));
    o.w = u.w * (0.5f * gate.w * (1.f + erff(gate.w * 0.70710678118654752f)));
    ((float4*)g)[idx] = o;
}

// =====================================================================
// tf32 mma GEMM, cp.async 3-stage pipeline, BK=32, raw fp32 bits as tf32
// =====================================================================
__inline__ __device__ void mma_tf32(float* c, const uint32_t* a, const uint32_t* b){
    asm volatile(
        "mma.sync.aligned.m16n8k8.row.col.f32.tf32.tf32.f32 "
        "{%0,%1,%2,%3}, {%4,%5,%6,%7}, {%8,%9}, {%0,%1,%2,%3};"
        : "+f"(c[0]), "+f"(c[1]), "+f"(c[2]), "+f"(c[3])
        : "r"(a[0]), "r"(a[1]), "r"(a[2]), "r"(a[3]), "r"(b[0]), "r"(b[1]));
}

template<int BM, int BN, bool TB>
__global__ void mma_gemm_k(const float* __restrict__ A, const float* __restrict__ Bm,
                           const float* __restrict__ bias, const float* __restrict__ res,
                           float* __restrict__ C,
                           int M, int N, int K, int lda, int ldb, int ldc,
                           int bdiv, long sAo, long sAi, long sBo, long sBi, long sCo, long sCi){
    constexpr int BK = 32, STAGES = 3;
    constexpr int WARPS_M = BM / 64, WARPS_N = BN / 32;
    constexpr int THREADS = WARPS_M * WARPS_N * 32;
    constexpr int LA_S = BK + 4;
    constexpr int BROWS = TB ? BN : BK;
    constexpr int LB_S  = TB ? (BK + 4) : (BN + 8);
    constexpr int A_WORDS = BM * LA_S;
    constexpr int B_WORDS = BROWS * LB_S;

    extern __shared__ float sm[];
    float* As = sm;
    float* Bs = sm + STAGES * A_WORDS;

    int z = blockIdx.z;
    long aoff = (long)(z / bdiv) * sAo + (long)(z % bdiv) * sAi;
    long boff = (long)(z / bdiv) * sBo + (long)(z % bdiv) * sBi;
    long coff = (long)(z / bdiv) * sCo + (long)(z % bdiv) * sCi;
    A += aoff; Bm += boff; C += coff;
    if (res) res += coff;

    int tid  = threadIdx.x;
    int warp = tid >> 5, lane = tid & 31;
    int g  = lane >> 2;
    int tg = lane & 3;
    int wm = (warp % WARPS_M) * 64;
    int wn = (warp / WARPS_M) * 32;
    int row0 = blockIdx.y * BM;
    int col0 = blockIdx.x * BN;

    float acc[4][4][4];
    #pragma unroll
    for (int i = 0; i < 4; i++)
        #pragma unroll
        for (int j = 0; j < 4; j++)
            #pragma unroll
            for (int r = 0; r < 4; r++) acc[i][j][r] = 0.f;

    auto loadA = [&](int s, int kt){
        constexpr int CH = BM * (BK / 4);
        float* base = As + s * A_WORDS;
        #pragma unroll
        for (int it = 0; it < CH / THREADS; it++){
            int c = tid + it * THREADS;
            int m  = c >> 3;
            int kc = (c & 7) << 2;
            int gm = row0 + m, gk = kt + kc;
            int bytes = (gm < M && gk < K) ? min(16, (K - gk) * 4) : 0;
            const float* src = bytes ? (A + (long)gm * lda + gk) : A;
            cp16(base + m * LA_S + kc, src, bytes);
        }
    };
    auto loadB = [&](int s, int kt){
        float* base = Bs + s * B_WORDS;
        if (TB){
            constexpr int CH = BN * (BK / 4);
            #pragma unroll
            for (int it = 0; it < CH / THREADS; it++){
                int c = tid + it * THREADS;
                int n  = c >> 3;
                int kc = (c & 7) << 2;
                int gn = col0 + n, gk = kt + kc;
                int bytes = (gn < N && gk < K) ? min(16, (K - gk) * 4) : 0;
                const float* src = bytes ? (Bm + (long)gn * ldb + gk) : Bm;
                cp16(base + n * LB_S + kc, src, bytes);
            }
        } else {
            constexpr int CPR = BN / 4;
            constexpr int CH = BK * CPR;
            #pragma unroll
            for (int it = 0; it < CH / THREADS; it++){
                int c = tid + it * THREADS;
                int kr = c / CPR;
                int nc = (c % CPR) << 2;
                int gk = kt + kr, gn = col0 + nc;
                int bytes = (gk < K && gn < N) ? min(16, (N - gn) * 4) : 0;
                const float* src = bytes ? (Bm + (long)gk * ldb + gn) : Bm;
                cp16(base + kr * LB_S + nc, src, bytes);
            }
        }
    };
    auto compute = [&](int s){
        const float* Ab = As + s * A_WORDS;
        const float* Bb = Bs + s * B_WORDS;
        #pragma unroll
        for (int ks = 0; ks < BK; ks += 8){
            uint32_t bf[4][2];
            #pragma unroll
            for (int j = 0; j < 4; j++){
                if (TB){
                    bf[j][0] = __float_as_uint(Bb[(wn + j * 8 + g) * LB_S + ks + tg]);
                    bf[j][1] = __float_as_uint(Bb[(wn + j * 8 + g) * LB_S + ks + tg + 4]);
                } else {
                    bf[j][0] = __float_as_uint(Bb[(ks + tg) * LB_S + wn + j * 8 + g]);
                    bf[j][1] = __float_as_uint(Bb[(ks + tg + 4) * LB_S + wn + j * 8 + g]);
                }
            }
            #pragma unroll
            for (int i = 0; i < 4; i++){
                int mr = wm + i * 16 + g;
                uint32_t af[4];
                af[0] = __float_as_uint(Ab[(mr    ) * LA_S + ks + tg]);
                af[1] = __float_as_uint(Ab[(mr + 8) * LA_S + ks + tg]);
                af[2] = __float_as_uint(Ab[(mr    ) * LA_S + ks + tg + 4]);
                af[3] = __float_as_uint(Ab[(mr + 8) * LA_S + ks + tg + 4]);
                #pragma unroll
                for (int j = 0; j < 4; j++)
                    mma_tf32(acc[i][j], af, bf[j]);
            }
        }
    };

    int nk = (K + BK - 1) / BK;

    // prologue: commit STAGES-1 groups
    #pragma unroll
    for (int s = 0; s < STAGES - 1; s++){
        if (s < nk){ loadA(s, s * BK); loadB(s, s * BK); }
        cp_commit();
    }

    for (int t = 0; t < nk; t++){
        // FIX (R3 bug): wait until the OLDEST pending group (stage t) is done.
        // With STAGES-1=2 groups committed, that means wait_group STAGES-2=1.
        cp_wait<STAGES - 2>();
        __syncthreads();
        int tn = t + STAGES - 1;
        if (tn < nk){ loadA(tn % STAGES, tn * BK); loadB(tn % STAGES, tn * BK); }
        cp_commit();
        compute(t % STAGES);
    }

    // epilogue
    #pragma unroll
    for (int i = 0; i < 4; i++){
        int r0 = row0 + wm + i * 16 + g;
        int r1 = r0 + 8;
        #pragma unroll
        for (int j = 0; j < 4; j++){
            int c0 = col0 + wn + j * 8 + 2 * tg;
            float* a4 = acc[i][j];
            if (r0 < M){
                if (c0 < N){
                    float v = a4[0];
                    if (bias) v += bias[c0];
                    if (res)  v += res[(long)r0 * ldc + c0];
                    C[(long)r0 * ldc + c0] = v;
                }
                if (c0 + 1 < N){
                    float v = a4[1];
                    if (bias) v += bias[c0 + 1];
                    if (res)  v += res[(long)r0 * ldc + c0 + 1];
                    C[(long)r0 * ldc + c0 + 1] = v;
                }
            }
            if (r1 < M){
                if (c0 < N){
                    float v = a4[2];
                    if (bias) v += bias[c0];
                    if (res)  v += res[(long)r1 * ldc + c0];
                    C[(long)r1 * ldc + c0] = v;
                }
                if (c0 + 1 < N){
                    float v = a4[3];
                    if (bias) v += bias[c0 + 1];
                    if (res)  v += res[(long)r1 * ldc + c0 + 1];
                    C[(long)r1 * ldc + c0 + 1] = v;
                }
            }
        }
    }
}

// ---------------- launch helper ----------------
template<int BM, int BN, bool TB>
static void launch_mma(dim3 grid,
                       const float* A, const float* Bm, const float* bias, const float* res,
                       float* C, int M, int N, int K, int lda, int ldb, int ldc,
                       int bdiv, long sAo, long sAi, long sBo, long sBi, long sCo, long sCi){
    constexpr int THREADS = (BM / 64) * (BN / 32) * 32;
    constexpr int SMEM = 3 * (BM * 36 + (TB ? BN * 36 : 32 * (BN + 8))) * 4;
    cudaFuncSetAttribute(mma_gemm_k<BM,BN,TB>, cudaFuncAttributeMaxDynamicSharedMemorySize, SMEM);
    mma_gemm_k<BM,BN,TB><<<grid, THREADS, SMEM>>>(A, Bm, bias, res, C, M, N, K, lda, ldb, ldc,
                                                  bdiv, sAo, sAi, sBo, sBi, sCo, sCi);
}

static void gemm_big(const float* A, const float* W, const float* bias, const float* res,
                     float* C, int M, int N, int K, int lda, int ldb, int ldc){
    dim3 g((N + 127) / 128, (M + 127) / 128, 1);
    launch_mma<128,128,false>(g, A, W, bias, res, C, M, N, K, lda, ldb, ldc,
                              1, 0, 0, 0, 0, 0, 0);
}

extern "C" void kernel_launch(void* const* d_in, const int* in_sizes, int n_in,
                              void* d_out, int out_size){
    (void)in_sizes; (void)n_in; (void)out_size;
    const float* x      = (const float*)d_in[0];
    const float* cond   = (const float*)d_in[1];
    const float* gn_s   = (const float*)d_in[2];
    const float* gn_b   = (const float*)d_in[3];
    const float* pin_w  = (const float*)d_in[4];
    const float* pin_b  = (const float*)d_in[5];
    const float* pout_w = (const float*)d_in[6];
    const float* pout_b = (const float*)d_in[7];
    const float* ln1_s  = (const float*)d_in[8];
    const float* ln1_b  = (const float*)d_in[9];
    const float* sa_wq  = (const float*)d_in[10];
    const float* sa_wk  = (const float*)d_in[11];
    const float* sa_wv  = (const float*)d_in[12];
    const float* sa_wo  = (const float*)d_in[13];
    const float* sa_bo  = (const float*)d_in[14];
    const float* ln2_s  = (const float*)d_in[15];
    const float* ln2_b  = (const float*)d_in[16];
    const float* ca_wq  = (const float*)d_in[17];
    const float* ca_wk  = (const float*)d_in[18];
    const float* ca_wv  = (const float*)d_in[19];
    const float* ca_wo  = (const float*)d_in[20];
    const float* ca_bo  = (const float*)d_in[21];
    const float* ln3_s  = (const float*)d_in[22];
    const float* ln3_b  = (const float*)d_in[23];
    const float* ff_w1  = (const float*)d_in[24];
    const float* ff_b1  = (const float*)d_in[25];
    const float* ff_w2  = (const float*)d_in[26];
    const float* ff_b2  = (const float*)d_in[27];
    float* out = (float*)d_out;

    float *p_t, *p_tn, *p_q, *p_k, *p_v, *p_ao, *p_attn, *p_ffh, *p_stats;
    cudaGetSymbolAddress((void**)&p_t,    g_t);
    cudaGetSymbolAddress((void**)&p_tn,   g_tn);
    cudaGetSymbolAddress((void**)&p_q,    g_q);
    cudaGetSymbolAddress((void**)&p_k,    g_k);
    cudaGetSymbolAddress((void**)&p_v,    g_v);
    cudaGetSymbolAddress((void**)&p_ao,   g_ao);
    cudaGetSymbolAddress((void**)&p_attn, g_attn);
    cudaGetSymbolAddress((void**)&p_ffh,  g_ffh);
    cudaGetSymbolAddress((void**)&p_stats,g_stats);

    gn_stats_k<<<BB * 32, 256>>>(x, p_stats);
    {
        dim3 g(SS / 32, CC / 32, BB);
        gn_apply_t_k<<<g, dim3(32, 8)>>>(x, p_stats, gn_s, gn_b, p_tn);
    }
    gemm_big(p_tn, pin_w, pin_b, nullptr, p_t, MM, CC, CC, CC, CC, CC);

    for (int l = 0; l < 2; l++){
        const float* wq = sa_wq + (long)l * CC * CC;
        const float* wk = sa_wk + (long)l * CC * CC;
        const float* wv = sa_wv + (long)l * CC * CC;
        const float* wo = sa_wo + (long)l * CC * CC;
        const float* bo = sa_bo + (long)l * CC;
        const float* cwq = ca_wq + (long)l * CC * CC;
        const float* cwk = ca_wk + (long)l * DCC * CC;
        const float* cwv = ca_wv + (long)l * DCC * CC;
        const float* cwo = ca_wo + (long)l * CC * CC;
        const float* cbo = ca_bo + (long)l * CC;
        const float* w1 = ff_w1 + (long)l * CC * 4096;
        const float* b1 = ff_b1 + (long)l * 4096;
        const float* w2 = ff_w2 + (long)l * 2048 * CC;
        const float* b2 = ff_b2 + (long)l * CC;

        // ---- self-attention ----
        layernorm_k<<<MM, 128>>>(p_t, ln1_s + l * CC, ln1_b + l * CC, p_tn);
        gemm_big(p_tn, wq, nullptr, nullptr, p_q, MM, CC, CC, CC, CC, CC);
        gemm_big(p_tn, wk, nullptr, nullptr, p_k, MM, CC, CC, CC, CC, CC);
        gemm_big(p_tn, wv, nullptr, nullptr, p_v, MM, CC, CC, CC, CC, CC);
        {   // QK^T per (b,h): M=1024 N=1024 K=64, NT
            dim3 g(8, 8, BB * NHH);
            launch_mma<128,128,true>(g, p_q, p_k, nullptr, nullptr, p_attn,
                1024, 1024, 64, CC, CC, 1024,
                NHH, (long)SS * CC, DHH, (long)SS * CC, DHH,
                (long)NHH * SS * SS, (long)SS * SS);
        }
        softmax4_k<8><<<(BB * NHH * SS + 7) / 8, 256>>>(p_attn, (long)BB * NHH * SS);
        {   // attn @ V per (b,h): M=1024 N=64 K=1024, NN
            dim3 g(1, 8, BB * NHH);
            launch_mma<128,64,false>(g, p_attn, p_v, nullptr, nullptr, p_ao,
                1024, 64, 1024, 1024, CC, CC,
                NHH, (long)NHH * SS * SS, (long)SS * SS,
                (long)SS * CC, DHH, (long)SS * CC, DHH);
        }
        gemm_big(p_ao, wo, bo, p_t, p_t, MM, CC, CC, CC, CC, CC);

        // ---- cross-attention ----
        layernorm_k<<<MM, 128>>>(p_t, ln2_s + l * CC, ln2_b + l * CC, p_tn);
        gemm_big(p_tn, cwq, nullptr, nullptr, p_q, MM, CC, CC, CC, CC, CC);
        gemm_big(cond, cwk, nullptr, nullptr, p_k, BB * NCC, CC, DCC, DCC, CC, CC);
        gemm_big(cond, cwv, nullptr, nullptr, p_v, BB * NCC, CC, DCC, DCC, CC, CC);
        {   // QK^T: M=1024 N=77 K=64, scores ld=80
            dim3 g(1, 8, BB * NHH);
            launch_mma<128,128,true>(g, p_q, p_k, nullptr, nullptr, p_attn,
                1024, NCC, 64, CC, CC, 80,
                NHH, (long)SS * CC, DHH, (long)NCC * CC, DHH,
                (long)NHH * SS * 80, (long)SS * 80);
        }
        softmax_k<3><<<(BB * NHH * SS + 7) / 8, 256>>>(p_attn, (long)BB * NHH * SS, NCC, 80);
        {   // attn @ V: M=1024 N=64 K=77
            dim3 g(1, 8, BB * NHH);
            launch_mma<128,64,false>(g, p_attn, p_v, nullptr, nullptr, p_ao,
                1024, 64, NCC, 80, CC, CC,
                NHH, (long)NHH * SS * 80, (long)SS * 80,
                (long)NCC * CC, DHH, (long)SS * CC, DHH);
        }
        gemm_big(p_ao, cwo, cbo, p_t, p_t, MM, CC, CC, CC, CC, CC);

        // ---- FFN (GEGLU) ----
        layernorm_k<<<MM, 128>>>(p_t, ln3_s + l * CC, ln3_b + l * CC, p_tn);
        gemm_big(p_tn, w1, b1, nullptr, p_ffh, MM, 4096, CC, CC, 4096, 4096);
        geglu4_k<<<(int)(((long)MM * 512 + 255) / 256), 256>>>(p_ffh, p_attn);
        gemm_big(p_attn, w2, b2, p_t, p_t, MM, CC, 2048, 2048, CC, CC);
    }

    gemm_big(p_t, pout_w, pout_b, nullptr, p_tn, MM, CC, CC, CC, CC, CC);
    {
        dim3 g(SS / 32, CC / 32, BB);
        out_add_t_k<<<g, dim3(32, 8)>>>(p_tn, x, out);
    }
}

// round 6
// speedup vs baseline: 3.8416x; 1.1482x over previous
#include <cuda_runtime.h>
#include <math.h>
#include <stdint.h>

// ---------------- problem constants ----------------
constexpr int BB   = 8;
constexpr int CC   = 512;
constexpr int SS   = 1024;
constexpr int NHH  = 8;
constexpr int DHH  = 64;
constexpr int NCC  = 77;
constexpr int DCC  = 768;
constexpr int MM   = BB * SS;  // 8192

// ---------------- scratch ----------------
__device__ __align__(256) float g_t   [ (long)MM * CC ];
__device__ __align__(256) float g_tn  [ (long)MM * CC ];
__device__ __align__(256) float g_q   [ (long)MM * CC ];
__device__ __align__(256) float g_k   [ (long)MM * CC ];
__device__ __align__(256) float g_v   [ (long)MM * CC ];
__device__ __align__(256) float g_ao  [ (long)MM * CC ];
__device__ __align__(256) float g_gg  [ (long)MM * 2048 ];   // GEGLU output
__device__ __align__(256) float g_ffh [ (long)MM * 4096 ];   // FFN hidden
__device__ __align__(256) float g_stats[ 2 * BB * 32 ];

// ---------------- reductions ----------------
__inline__ __device__ float warpSum(float v){
    #pragma unroll
    for (int o = 16; o > 0; o >>= 1) v += __shfl_xor_sync(0xffffffffu, v, o);
    return v;
}

// ---------------- cp.async helpers ----------------
__device__ __forceinline__ uint32_t smem_u32(const void* p){
    return (uint32_t)__cvta_generic_to_shared(p);
}
__device__ __forceinline__ void cp16(void* dst, const void* src, int bytes){
    asm volatile("cp.async.cg.shared.global [%0], [%1], 16, %2;\n"
                 :: "r"(smem_u32(dst)), "l"(src), "r"(bytes));
}
__device__ __forceinline__ void cp_commit(){ asm volatile("cp.async.commit_group;\n"); }
template<int N> __device__ __forceinline__ void cp_wait(){
    asm volatile("cp.async.wait_group %0;\n" :: "n"(N));
}

// ---------------- mma tf32 ----------------
__inline__ __device__ void mma_tf32(float* c, const uint32_t* a, const uint32_t* b){
    asm volatile(
        "mma.sync.aligned.m16n8k8.row.col.f32.tf32.tf32.f32 "
        "{%0,%1,%2,%3}, {%4,%5,%6,%7}, {%8,%9}, {%0,%1,%2,%3};"
        : "+f"(c[0]), "+f"(c[1]), "+f"(c[2]), "+f"(c[3])
        : "r"(a[0]), "r"(a[1]), "r"(a[2]), "r"(a[3]), "r"(b[0]), "r"(b[1]));
}
__inline__ __device__ void mma_tf32f(float* c, const float* a, float b0, float b1){
    uint32_t au[4] = {__float_as_uint(a[0]), __float_as_uint(a[1]),
                      __float_as_uint(a[2]), __float_as_uint(a[3])};
    uint32_t bu[2] = {__float_as_uint(b0), __float_as_uint(b1)};
    mma_tf32(c, au, bu);
}

// ---------------- groupnorm stats ----------------
__global__ void gn_stats_k(const float* __restrict__ x, float* __restrict__ stats){
    long base = (long)blockIdx.x * 16384;
    float s = 0.f, q = 0.f;
    for (int i = threadIdx.x; i < 16384; i += blockDim.x){
        float v = x[base + i];
        s += v; q += v * v;
    }
    __shared__ float shs[8], shq[8];
    s = warpSum(s); q = warpSum(q);
    int w = threadIdx.x >> 5, l = threadIdx.x & 31;
    if (l == 0){ shs[w] = s; shq[w] = q; }
    __syncthreads();
    if (threadIdx.x < 32){
        s = (l < 8) ? shs[l] : 0.f;
        q = (l < 8) ? shq[l] : 0.f;
        s = warpSum(s); q = warpSum(q);
        if (l == 0){
            float mean = s * (1.f / 16384.f);
            float var  = q * (1.f / 16384.f) - mean * mean;
            stats[2 * blockIdx.x]     = mean;
            stats[2 * blockIdx.x + 1] = rsqrtf(var + 1e-6f);
        }
    }
}

// ---------------- groupnorm apply + transpose ----------------
__global__ void gn_apply_t_k(const float* __restrict__ x, const float* __restrict__ stats,
                             const float* __restrict__ gs, const float* __restrict__ gb,
                             float* __restrict__ out){
    __shared__ float tile[32][33];
    int b = blockIdx.z, c0 = blockIdx.y * 32, p0 = blockIdx.x * 32;
    int tx = threadIdx.x, ty = threadIdx.y;
    #pragma unroll
    for (int r = 0; r < 4; r++){
        int c = c0 + ty + r * 8;
        float v = x[((long)b * CC + c) * SS + p0 + tx];
        int grp = b * 32 + (c >> 4);
        v = (v - stats[2 * grp]) * stats[2 * grp + 1] * gs[c] + gb[c];
        tile[ty + r * 8][tx] = v;
    }
    __syncthreads();
    #pragma unroll
    for (int r = 0; r < 4; r++){
        int p = p0 + ty + r * 8;
        out[((long)b * SS + p) * CC + c0 + tx] = tile[tx][ty + r * 8];
    }
}

// ---------------- final transpose + x_in residual ----------------
__global__ void out_add_t_k(const float* __restrict__ z, const float* __restrict__ x,
                            float* __restrict__ out){
    __shared__ float tile[32][33];
    int b = blockIdx.z, c0 = blockIdx.y * 32, p0 = blockIdx.x * 32;
    int tx = threadIdx.x, ty = threadIdx.y;
    #pragma unroll
    for (int r = 0; r < 4; r++){
        int p = p0 + ty + r * 8;
        tile[ty + r * 8][tx] = z[((long)b * SS + p) * CC + c0 + tx];
    }
    __syncthreads();
    #pragma unroll
    for (int r = 0; r < 4; r++){
        int c = c0 + ty + r * 8;
        long o = ((long)b * CC + c) * SS + p0 + tx;
        out[o] = tile[tx][ty + r * 8] + x[o];
    }
}

// ---------------- layernorm ----------------
__global__ void layernorm_k(const float* __restrict__ in, const float* __restrict__ sc,
                            const float* __restrict__ bi, float* __restrict__ out){
    long row = blockIdx.x;
    const float4* x4 = (const float4*)(in + row * CC);
    float4 xv = x4[threadIdx.x];
    float s = xv.x + xv.y + xv.z + xv.w;
    float q = xv.x*xv.x + xv.y*xv.y + xv.z*xv.z + xv.w*xv.w;
    __shared__ float shs[4], shq[4];
    s = warpSum(s); q = warpSum(q);
    int w = threadIdx.x >> 5, l = threadIdx.x & 31;
    if (l == 0){ shs[w] = s; shq[w] = q; }
    __syncthreads();
    if (threadIdx.x < 32){
        float a = (l < 4) ? shs[l] : 0.f;
        float b2 = (l < 4) ? shq[l] : 0.f;
        a = warpSum(a); b2 = warpSum(b2);
        if (l == 0){ shs[0] = a; shq[0] = b2; }
    }
    __syncthreads();
    float mean = shs[0] * (1.f / 512.f);
    float rstd = rsqrtf(shq[0] * (1.f / 512.f) - mean * mean + 1e-5f);
    float4 sv = ((const float4*)sc)[threadIdx.x];
    float4 bv = ((const float4*)bi)[threadIdx.x];
    float4 o;
    o.x = (xv.x - mean) * rstd * sv.x + bv.x;
    o.y = (xv.y - mean) * rstd * sv.y + bv.y;
    o.z = (xv.z - mean) * rstd * sv.z + bv.z;
    o.w = (xv.w - mean) * rstd * sv.w + bv.w;
    ((float4*)(out + row * CC))[threadIdx.x] = o;
}

// ---------------- GEGLU (float4) ----------------
__global__ void geglu4_k(const float* __restrict__ h, float* __restrict__ g){
    long idx = (long)blockIdx.x * blockDim.x + threadIdx.x;
    if (idx >= (long)MM * 512) return;
    long m = idx >> 9;
    int  i = (int)(idx & 511);
    const float4* h4 = (const float4*)h;
    float4 u    = h4[m * 1024 + i];
    float4 gate = h4[m * 1024 + 512 + i];
    float4 o;
    o.x = u.x * (0.5f * gate.x * (1.f + erff(gate.x * 0.70710678118654752f)));
    o.y = u.y * (0.5f * gate.y * (1.f + erff(gate.y * 0.70710678118654752f)));
    o.z = u.z * (0.5f * gate.z * (1.f + erff(gate.z * 0.70710678118654752f)));
    o.w = u.w * (0.5f * gate.w * (1.f + erff(gate.w * 0.70710678118654752f)));
    ((float4*)g)[idx] = o;
}

// =====================================================================
// Flash attention (tf32 mma, online softmax).
// Block: 256 threads = 8 warps, 16 q-rows each -> 128 q-rows per block.
// FIX (R5 bug): P gets a DEDICATED smem region with stride LP=TKV+4.
// (R5 reused the Q slice, stride 68 < TKV=80 for cross-attn -> overflow.)
// =====================================================================
template<int TKV, int KVLEN, int NTILES, int NSTAGE>
__global__ void flash_k(const float* __restrict__ Q, const float* __restrict__ K,
                        const float* __restrict__ V, float* __restrict__ O,
                        long kv_bstride){
    constexpr int NT = TKV / 8;
    constexpr int LQ = 68, LK = 68, LV = 72, LP = TKV + 4;
    extern __shared__ float sm[];
    float* Qs = sm;                                  // 128*LQ
    float* Ks = sm + 128 * LQ;                       // NSTAGE*TKV*LK
    float* Vs = Ks + NSTAGE * TKV * LK;              // NSTAGE*TKV*LV
    float* Pall = Vs + NSTAGE * TKV * LV;            // 128*LP (dedicated P)

    int tid = threadIdx.x;
    int w = tid >> 5, lane = tid & 31;
    int g = lane >> 2, tg = lane & 3;
    int qt = blockIdx.x;
    int b = blockIdx.y / NHH, h = blockIdx.y % NHH;

    const float* Qb = Q + ((long)(b * SS + qt * 128)) * CC + h * DHH;
    const float* Kb = K + (long)b * kv_bstride + h * DHH;
    const float* Vb = V + (long)b * kv_bstride + h * DHH;

    auto loadQ = [&](){
        #pragma unroll
        for (int i = 0; i < 8; i++){
            int c = tid + i * 256;
            int row = c >> 4, d4 = (c & 15) << 2;
            cp16(Qs + row * LQ + d4, Qb + (long)row * CC + d4, 16);
        }
    };
    auto loadKV = [&](int s, int t){
        constexpr int CH = TKV * 16;
        #pragma unroll
        for (int i = 0; i < CH / 256; i++){
            int c = tid + i * 256;
            int row = c >> 4, d4 = (c & 15) << 2;
            int r = t * TKV + row;
            int by = (r < KVLEN) ? 16 : 0;
            const float* ksrc = by ? (Kb + (long)r * CC + d4) : Kb;
            const float* vsrc = by ? (Vb + (long)r * CC + d4) : Vb;
            cp16(Ks + s * TKV * LK + row * LK + d4, ksrc, by);
            cp16(Vs + s * TKV * LV + row * LV + d4, vsrc, by);
        }
    };

    loadQ(); loadKV(0, 0); cp_commit();
    if (NTILES > 1){ loadKV(1, 1); cp_commit(); }

    float qa[8][4];
    float oacc[8][4];
    #pragma unroll
    for (int j = 0; j < 8; j++)
        #pragma unroll
        for (int r = 0; r < 4; r++) oacc[j][r] = 0.f;
    float m0 = -1e30f, m1 = -1e30f, l0 = 0.f, l1 = 0.f;
    float* Ps = Pall + w * 16 * LP;      // per-warp 16 x LP slice

    for (int t = 0; t < NTILES; t++){
        if (t + 1 < NTILES) cp_wait<1>(); else cp_wait<0>();
        __syncthreads();
        if (t == 0){
            const float* qsw = Qs + w * 16 * LQ;
            #pragma unroll
            for (int kk = 0; kk < 8; kk++){
                qa[kk][0] = qsw[(g    ) * LQ + kk * 8 + tg    ];
                qa[kk][1] = qsw[(g + 8) * LQ + kk * 8 + tg    ];
                qa[kk][2] = qsw[(g    ) * LQ + kk * 8 + tg + 4];
                qa[kk][3] = qsw[(g + 8) * LQ + kk * 8 + tg + 4];
            }
            __syncwarp();
        }
        const float* Kt = Ks + (t % NSTAGE) * TKV * LK;
        const float* Vt = Vs + (t % NSTAGE) * TKV * LV;

        // ---- S = Q K^T ----
        float sacc[NT][4];
        #pragma unroll
        for (int j = 0; j < NT; j++)
            #pragma unroll
            for (int r = 0; r < 4; r++) sacc[j][r] = 0.f;
        #pragma unroll
        for (int j = 0; j < NT; j++){
            const float* krow = Kt + (j * 8 + g) * LK;
            #pragma unroll
            for (int kk = 0; kk < 8; kk++)
                mma_tf32f(sacc[j], qa[kk], krow[kk * 8 + tg], krow[kk * 8 + tg + 4]);
        }
        // ---- mask ragged last tile ----
        if (KVLEN < NTILES * TKV && t == NTILES - 1){
            #pragma unroll
            for (int j = 0; j < NT; j++){
                int col = t * TKV + j * 8 + 2 * tg;
                if (col     >= KVLEN){ sacc[j][0] = -1e30f; sacc[j][2] = -1e30f; }
                if (col + 1 >= KVLEN){ sacc[j][1] = -1e30f; sacc[j][3] = -1e30f; }
            }
        }
        // ---- online softmax ----
        float rm0 = -1e30f, rm1 = -1e30f;
        #pragma unroll
        for (int j = 0; j < NT; j++){
            rm0 = fmaxf(rm0, fmaxf(sacc[j][0], sacc[j][1]));
            rm1 = fmaxf(rm1, fmaxf(sacc[j][2], sacc[j][3]));
        }
        rm0 = fmaxf(rm0, __shfl_xor_sync(0xffffffffu, rm0, 1));
        rm0 = fmaxf(rm0, __shfl_xor_sync(0xffffffffu, rm0, 2));
        rm1 = fmaxf(rm1, __shfl_xor_sync(0xffffffffu, rm1, 1));
        rm1 = fmaxf(rm1, __shfl_xor_sync(0xffffffffu, rm1, 2));
        float mn0 = fmaxf(m0, rm0), mn1 = fmaxf(m1, rm1);
        float a0 = __expf(m0 - mn0), a1 = __expf(m1 - mn1);
        float rs0 = 0.f, rs1 = 0.f;
        #pragma unroll
        for (int j = 0; j < NT; j++){
            sacc[j][0] = __expf(sacc[j][0] - mn0);
            sacc[j][1] = __expf(sacc[j][1] - mn0);
            sacc[j][2] = __expf(sacc[j][2] - mn1);
            sacc[j][3] = __expf(sacc[j][3] - mn1);
            rs0 += sacc[j][0] + sacc[j][1];
            rs1 += sacc[j][2] + sacc[j][3];
        }
        rs0 += __shfl_xor_sync(0xffffffffu, rs0, 1);
        rs0 += __shfl_xor_sync(0xffffffffu, rs0, 2);
        rs1 += __shfl_xor_sync(0xffffffffu, rs1, 1);
        rs1 += __shfl_xor_sync(0xffffffffu, rs1, 2);
        l0 = l0 * a0 + rs0;  l1 = l1 * a1 + rs1;
        m0 = mn0;  m1 = mn1;
        #pragma unroll
        for (int jn = 0; jn < 8; jn++){
            oacc[jn][0] *= a0; oacc[jn][1] *= a0;
            oacc[jn][2] *= a1; oacc[jn][3] *= a1;
        }
        // ---- stage P in dedicated smem slice ----
        #pragma unroll
        for (int j = 0; j < NT; j++){
            Ps[(g    ) * LP + j * 8 + 2 * tg    ] = sacc[j][0];
            Ps[(g    ) * LP + j * 8 + 2 * tg + 1] = sacc[j][1];
            Ps[(g + 8) * LP + j * 8 + 2 * tg    ] = sacc[j][2];
            Ps[(g + 8) * LP + j * 8 + 2 * tg + 1] = sacc[j][3];
        }
        __syncwarp();
        // ---- O += P V ----
        #pragma unroll
        for (int kk = 0; kk < NT; kk++){
            float pa[4];
            pa[0] = Ps[(g    ) * LP + kk * 8 + tg    ];
            pa[1] = Ps[(g + 8) * LP + kk * 8 + tg    ];
            pa[2] = Ps[(g    ) * LP + kk * 8 + tg + 4];
            pa[3] = Ps[(g + 8) * LP + kk * 8 + tg + 4];
            #pragma unroll
            for (int jn = 0; jn < 8; jn++){
                float vb0 = Vt[(kk * 8 + tg    ) * LV + jn * 8 + g];
                float vb1 = Vt[(kk * 8 + tg + 4) * LV + jn * 8 + g];
                mma_tf32f(oacc[jn], pa, vb0, vb1);
            }
        }
        __syncthreads();
        if (t + 2 < NTILES) loadKV(t % 2, t + 2);
        cp_commit();
    }

    float inv0 = 1.f / l0, inv1 = 1.f / l1;
    float* Ob = O + ((long)(b * SS + qt * 128 + w * 16)) * CC + h * DHH;
    #pragma unroll
    for (int jn = 0; jn < 8; jn++){
        int col = jn * 8 + 2 * tg;
        Ob[(long)(g    ) * CC + col    ] = oacc[jn][0] * inv0;
        Ob[(long)(g    ) * CC + col + 1] = oacc[jn][1] * inv0;
        Ob[(long)(g + 8) * CC + col    ] = oacc[jn][2] * inv1;
        Ob[(long)(g + 8) * CC + col + 1] = oacc[jn][3] * inv1;
    }
}

// =====================================================================
// tf32 mma GEMM, cp.async 3-stage pipeline (R4, verified)
// =====================================================================
template<int BM, int BN, bool TB>
__global__ void mma_gemm_k(const float* __restrict__ A, const float* __restrict__ Bm,
                           const float* __restrict__ bias, const float* __restrict__ res,
                           float* __restrict__ C,
                           int M, int N, int K, int lda, int ldb, int ldc){
    constexpr int BK = 32, STAGES = 3;
    constexpr int WARPS_M = BM / 64, WARPS_N = BN / 32;
    constexpr int THREADS = WARPS_M * WARPS_N * 32;
    constexpr int LA_S = BK + 4;
    constexpr int BROWS = TB ? BN : BK;
    constexpr int LB_S  = TB ? (BK + 4) : (BN + 8);
    constexpr int A_WORDS = BM * LA_S;
    constexpr int B_WORDS = BROWS * LB_S;

    extern __shared__ float sm[];
    float* As = sm;
    float* Bs = sm + STAGES * A_WORDS;

    int tid  = threadIdx.x;
    int warp = tid >> 5, lane = tid & 31;
    int g  = lane >> 2;
    int tg = lane & 3;
    int wm = (warp % WARPS_M) * 64;
    int wn = (warp / WARPS_M) * 32;
    int row0 = blockIdx.y * BM;
    int col0 = blockIdx.x * BN;

    float acc[4][4][4];
    #pragma unroll
    for (int i = 0; i < 4; i++)
        #pragma unroll
        for (int j = 0; j < 4; j++)
            #pragma unroll
            for (int r = 0; r < 4; r++) acc[i][j][r] = 0.f;

    auto loadA = [&](int s, int kt){
        constexpr int CH = BM * (BK / 4);
        float* base = As + s * A_WORDS;
        #pragma unroll
        for (int it = 0; it < CH / THREADS; it++){
            int c = tid + it * THREADS;
            int m  = c >> 3;
            int kc = (c & 7) << 2;
            int gm = row0 + m, gk = kt + kc;
            int bytes = (gm < M && gk < K) ? min(16, (K - gk) * 4) : 0;
            const float* src = bytes ? (A + (long)gm * lda + gk) : A;
            cp16(base + m * LA_S + kc, src, bytes);
        }
    };
    auto loadB = [&](int s, int kt){
        float* base = Bs + s * B_WORDS;
        if (TB){
            constexpr int CH = BN * (BK / 4);
            #pragma unroll
            for (int it = 0; it < CH / THREADS; it++){
                int c = tid + it * THREADS;
                int n  = c >> 3;
                int kc = (c & 7) << 2;
                int gn = col0 + n, gk = kt + kc;
                int bytes = (gn < N && gk < K) ? min(16, (K - gk) * 4) : 0;
                const float* src = bytes ? (Bm + (long)gn * ldb + gk) : Bm;
                cp16(base + n * LB_S + kc, src, bytes);
            }
        } else {
            constexpr int CPR = BN / 4;
            constexpr int CH = BK * CPR;
            #pragma unroll
            for (int it = 0; it < CH / THREADS; it++){
                int c = tid + it * THREADS;
                int kr = c / CPR;
                int nc = (c % CPR) << 2;
                int gk = kt + kr, gn = col0 + nc;
                int bytes = (gk < K && gn < N) ? min(16, (N - gn) * 4) : 0;
                const float* src = bytes ? (Bm + (long)gk * ldb + gn) : Bm;
                cp16(base + kr * LB_S + nc, src, bytes);
            }
        }
    };
    auto compute = [&](int s){
        const float* Ab = As + s * A_WORDS;
        const float* Bb = Bs + s * B_WORDS;
        #pragma unroll
        for (int ks = 0; ks < BK; ks += 8){
            uint32_t bf[4][2];
            #pragma unroll
            for (int j = 0; j < 4; j++){
                if (TB){
                    bf[j][0] = __float_as_uint(Bb[(wn + j * 8 + g) * LB_S + ks + tg]);
                    bf[j][1] = __float_as_uint(Bb[(wn + j * 8 + g) * LB_S + ks + tg + 4]);
                } else {
                    bf[j][0] = __float_as_uint(Bb[(ks + tg) * LB_S + wn + j * 8 + g]);
                    bf[j][1] = __float_as_uint(Bb[(ks + tg + 4) * LB_S + wn + j * 8 + g]);
                }
            }
            #pragma unroll
            for (int i = 0; i < 4; i++){
                int mr = wm + i * 16 + g;
                uint32_t af[4];
                af[0] = __float_as_uint(Ab[(mr    ) * LA_S + ks + tg]);
                af[1] = __float_as_uint(Ab[(mr + 8) * LA_S + ks + tg]);
                af[2] = __float_as_uint(Ab[(mr    ) * LA_S + ks + tg + 4]);
                af[3] = __float_as_uint(Ab[(mr + 8) * LA_S + ks + tg + 4]);
                #pragma unroll
                for (int j = 0; j < 4; j++)
                    mma_tf32(acc[i][j], af, bf[j]);
            }
        }
    };

    int nk = (K + BK - 1) / BK;
    #pragma unroll
    for (int s = 0; s < STAGES - 1; s++){
        if (s < nk){ loadA(s, s * BK); loadB(s, s * BK); }
        cp_commit();
    }
    for (int t = 0; t < nk; t++){
        cp_wait<STAGES - 2>();
        __syncthreads();
        int tn = t + STAGES - 1;
        if (tn < nk){ loadA(tn % STAGES, tn * BK); loadB(tn % STAGES, tn * BK); }
        cp_commit();
        compute(t % STAGES);
    }

    #pragma unroll
    for (int i = 0; i < 4; i++){
        int r0 = row0 + wm + i * 16 + g;
        int r1 = r0 + 8;
        #pragma unroll
        for (int j = 0; j < 4; j++){
            int c0 = col0 + wn + j * 8 + 2 * tg;
            float* a4 = acc[i][j];
            if (r0 < M){
                if (c0 < N){
                    float v = a4[0];
                    if (bias) v += bias[c0];
                    if (res)  v += res[(long)r0 * ldc + c0];
                    C[(long)r0 * ldc + c0] = v;
                }
                if (c0 + 1 < N){
                    float v = a4[1];
                    if (bias) v += bias[c0 + 1];
                    if (res)  v += res[(long)r0 * ldc + c0 + 1];
                    C[(long)r0 * ldc + c0 + 1] = v;
                }
            }
            if (r1 < M){
                if (c0 < N){
                    float v = a4[2];
                    if (bias) v += bias[c0];
                    if (res)  v += res[(long)r1 * ldc + c0];
                    C[(long)r1 * ldc + c0] = v;
                }
                if (c0 + 1 < N){
                    float v = a4[3];
                    if (bias) v += bias[c0 + 1];
                    if (res)  v += res[(long)r1 * ldc + c0 + 1];
                    C[(long)r1 * ldc + c0 + 1] = v;
                }
            }
        }
    }
}

// ---------------- launch helper ----------------
static void gemm_big(const float* A, const float* W, const float* bias, const float* res,
                     float* C, int M, int N, int K, int lda, int ldb, int ldc){
    constexpr int SMEM = 3 * (128 * 36 + 32 * (128 + 8)) * 4;
    cudaFuncSetAttribute(mma_gemm_k<128,128,false>,
                         cudaFuncAttributeMaxDynamicSharedMemorySize, SMEM);
    dim3 g((N + 127) / 128, (M + 127) / 128, 1);
    mma_gemm_k<128,128,false><<<g, 256, SMEM>>>(A, W, bias, res, C, M, N, K, lda, ldb, ldc);
}

extern "C" void kernel_launch(void* const* d_in, const int* in_sizes, int n_in,
                              void* d_out, int out_size){
    (void)in_sizes; (void)n_in; (void)out_size;
    const float* x      = (const float*)d_in[0];
    const float* cond   = (const float*)d_in[1];
    const float* gn_s   = (const float*)d_in[2];
    const float* gn_b   = (const float*)d_in[3];
    const float* pin_w  = (const float*)d_in[4];
    const float* pin_b  = (const float*)d_in[5];
    const float* pout_w = (const float*)d_in[6];
    const float* pout_b = (const float*)d_in[7];
    const float* ln1_s  = (const float*)d_in[8];
    const float* ln1_b  = (const float*)d_in[9];
    const float* sa_wq  = (const float*)d_in[10];
    const float* sa_wk  = (const float*)d_in[11];
    const float* sa_wv  = (const float*)d_in[12];
    const float* sa_wo  = (const float*)d_in[13];
    const float* sa_bo  = (const float*)d_in[14];
    const float* ln2_s  = (const float*)d_in[15];
    const float* ln2_b  = (const float*)d_in[16];
    const float* ca_wq  = (const float*)d_in[17];
    const float* ca_wk  = (const float*)d_in[18];
    const float* ca_wv  = (const float*)d_in[19];
    const float* ca_wo  = (const float*)d_in[20];
    const float* ca_bo  = (const float*)d_in[21];
    const float* ln3_s  = (const float*)d_in[22];
    const float* ln3_b  = (const float*)d_in[23];
    const float* ff_w1  = (const float*)d_in[24];
    const float* ff_b1  = (const float*)d_in[25];
    const float* ff_w2  = (const float*)d_in[26];
    const float* ff_b2  = (const float*)d_in[27];
    float* out = (float*)d_out;

    float *p_t, *p_tn, *p_q, *p_k, *p_v, *p_ao, *p_gg, *p_ffh, *p_stats;
    cudaGetSymbolAddress((void**)&p_t,    g_t);
    cudaGetSymbolAddress((void**)&p_tn,   g_tn);
    cudaGetSymbolAddress((void**)&p_q,    g_q);
    cudaGetSymbolAddress((void**)&p_k,    g_k);
    cudaGetSymbolAddress((void**)&p_v,    g_v);
    cudaGetSymbolAddress((void**)&p_ao,   g_ao);
    cudaGetSymbolAddress((void**)&p_gg,   g_gg);
    cudaGetSymbolAddress((void**)&p_ffh,  g_ffh);
    cudaGetSymbolAddress((void**)&p_stats,g_stats);

    // flash smem sizes (bytes): Q + NSTAGE*(K+V) + dedicated P
    constexpr int SM_SELF  = (128 * 68 + 2 * 64 * 68 + 2 * 64 * 72 + 128 * (64 + 4)) * 4;
    constexpr int SM_CROSS = (128 * 68 + 80 * 68 + 80 * 72 + 128 * (80 + 4)) * 4;
    cudaFuncSetAttribute(flash_k<64, 1024, 16, 2>,
                         cudaFuncAttributeMaxDynamicSharedMemorySize, SM_SELF);
    cudaFuncSetAttribute(flash_k<80, 77, 1, 1>,
                         cudaFuncAttributeMaxDynamicSharedMemorySize, SM_CROSS);

    gn_stats_k<<<BB * 32, 256>>>(x, p_stats);
    {
        dim3 g(SS / 32, CC / 32, BB);
        gn_apply_t_k<<<g, dim3(32, 8)>>>(x, p_stats, gn_s, gn_b, p_tn);
    }
    gemm_big(p_tn, pin_w, pin_b, nullptr, p_t, MM, CC, CC, CC, CC, CC);

    for (int l = 0; l < 2; l++){
        const float* wq = sa_wq + (long)l * CC * CC;
        const float* wk = sa_wk + (long)l * CC * CC;
        const float* wv = sa_wv + (long)l * CC * CC;
        const float* wo = sa_wo + (long)l * CC * CC;
        const float* bo = sa_bo + (long)l * CC;
        const float* cwq = ca_wq + (long)l * CC * CC;
        const float* cwk = ca_wk + (long)l * DCC * CC;
        const float* cwv = ca_wv + (long)l * DCC * CC;
        const float* cwo = ca_wo + (long)l * CC * CC;
        const float* cbo = ca_bo + (long)l * CC;
        const float* w1 = ff_w1 + (long)l * CC * 4096;
        const float* b1 = ff_b1 + (long)l * 4096;
        const float* w2 = ff_w2 + (long)l * 2048 * CC;
        const float* b2 = ff_b2 + (long)l * CC;

        // ---- self-attention ----
        layernorm_k<<<MM, 128>>>(p_t, ln1_s + l * CC, ln1_b + l * CC, p_tn);
        gemm_big(p_tn, wq, nullptr, nullptr, p_q, MM, CC, CC, CC, CC, CC);
        gemm_big(p_tn, wk, nullptr, nullptr, p_k, MM, CC, CC, CC, CC, CC);
        gemm_big(p_tn, wv, nullptr, nullptr, p_v, MM, CC, CC, CC, CC, CC);
        flash_k<64, 1024, 16, 2><<<dim3(SS / 128, BB * NHH), 256, SM_SELF>>>(
            p_q, p_k, p_v, p_ao, (long)SS * CC);
        gemm_big(p_ao, wo, bo, p_t, p_t, MM, CC, CC, CC, CC, CC);

        // ---- cross-attention ----
        layernorm_k<<<MM, 128>>>(p_t, ln2_s + l * CC, ln2_b + l * CC, p_tn);
        gemm_big(p_tn, cwq, nullptr, nullptr, p_q, MM, CC, CC, CC, CC, CC);
        gemm_big(cond, cwk, nullptr, nullptr, p_k, BB * NCC, CC, DCC, DCC, CC, CC);
        gemm_big(cond, cwv, nullptr, nullptr, p_v, BB * NCC, CC, DCC, DCC, CC, CC);
        flash_k<80, 77, 1, 1><<<dim3(SS / 128, BB * NHH), 256, SM_CROSS>>>(
            p_q, p_k, p_v, p_ao, (long)NCC * CC);
        gemm_big(p_ao, cwo, cbo, p_t, p_t, MM, CC, CC, CC, CC, CC);

        // ---- FFN (GEGLU) ----
        layernorm_k<<<MM, 128>>>(p_t, ln3_s + l * CC, ln3_b + l * CC, p_tn);
        gemm_big(p_tn, w1, b1, nullptr, p_ffh, MM, 4096, CC, CC, 4096, 4096);
        geglu4_k<<<(int)(((long)MM * 512 + 255) / 256), 256>>>(p_ffh, p_gg);
        gemm_big(p_gg, w2, b2, p_t, p_t, MM, CC, 2048, 2048, CC, CC);
    }

    gemm_big(p_t, pout_w, pout_b, nullptr, p_tn, MM, CC, CC, CC, CC, CC);
    {
        dim3 g(SS / 32, CC / 32, BB);
        out_add_t_k<<<g, dim3(32, 8)>>>(p_tn, x, out);
    }
}

// round 7
// speedup vs baseline: 3.9747x; 1.0346x over previous
#include <cuda_runtime.h>
#include <math.h>
#include <stdint.h>

// ---------------- problem constants ----------------
constexpr int BB   = 8;
constexpr int CC   = 512;
constexpr int SS   = 1024;
constexpr int NHH  = 8;
constexpr int DHH  = 64;
constexpr int NCC  = 77;
constexpr int DCC  = 768;
constexpr int MM   = BB * SS;  // 8192

// ---------------- scratch ----------------
__device__ __align__(256) float g_t   [ (long)MM * CC ];
__device__ __align__(256) float g_tn  [ (long)MM * CC ];
__device__ __align__(256) float g_q   [ (long)MM * CC ];
__device__ __align__(256) float g_k   [ (long)MM * CC ];
__device__ __align__(256) float g_v   [ (long)MM * CC ];
__device__ __align__(256) float g_ao  [ (long)MM * CC ];
__device__ __align__(256) float g_gg  [ (long)MM * 2048 ];   // GEGLU output
__device__ __align__(256) float g_stats[ 2 * BB * 32 ];

// ---------------- reductions ----------------
__inline__ __device__ float warpSum(float v){
    #pragma unroll
    for (int o = 16; o > 0; o >>= 1) v += __shfl_xor_sync(0xffffffffu, v, o);
    return v;
}

// ---------------- cp.async helpers ----------------
__device__ __forceinline__ uint32_t smem_u32(const void* p){
    return (uint32_t)__cvta_generic_to_shared(p);
}
__device__ __forceinline__ void cp16(void* dst, const void* src, int bytes){
    asm volatile("cp.async.cg.shared.global [%0], [%1], 16, %2;\n"
                 :: "r"(smem_u32(dst)), "l"(src), "r"(bytes));
}
__device__ __forceinline__ void cp_commit(){ asm volatile("cp.async.commit_group;\n"); }
template<int N> __device__ __forceinline__ void cp_wait(){
    asm volatile("cp.async.wait_group %0;\n" :: "n"(N));
}

// ---------------- mma tf32 ----------------
__inline__ __device__ void mma_tf32(float* c, const uint32_t* a, const uint32_t* b){
    asm volatile(
        "mma.sync.aligned.m16n8k8.row.col.f32.tf32.tf32.f32 "
        "{%0,%1,%2,%3}, {%4,%5,%6,%7}, {%8,%9}, {%0,%1,%2,%3};"
        : "+f"(c[0]), "+f"(c[1]), "+f"(c[2]), "+f"(c[3])
        : "r"(a[0]), "r"(a[1]), "r"(a[2]), "r"(a[3]), "r"(b[0]), "r"(b[1]));
}
__inline__ __device__ void mma_tf32f(float* c, const float* a, float b0, float b1){
    uint32_t au[4] = {__float_as_uint(a[0]), __float_as_uint(a[1]),
                      __float_as_uint(a[2]), __float_as_uint(a[3])};
    uint32_t bu[2] = {__float_as_uint(b0), __float_as_uint(b1)};
    mma_tf32(c, au, bu);
}

__inline__ __device__ float gelu_exact(float x){
    return 0.5f * x * (1.f + erff(x * 0.70710678118654752f));
}

// ---------------- groupnorm stats ----------------
__global__ void gn_stats_k(const float* __restrict__ x, float* __restrict__ stats){
    long base = (long)blockIdx.x * 16384;
    float s = 0.f, q = 0.f;
    for (int i = threadIdx.x; i < 16384; i += blockDim.x){
        float v = x[base + i];
        s += v; q += v * v;
    }
    __shared__ float shs[8], shq[8];
    s = warpSum(s); q = warpSum(q);
    int w = threadIdx.x >> 5, l = threadIdx.x & 31;
    if (l == 0){ shs[w] = s; shq[w] = q; }
    __syncthreads();
    if (threadIdx.x < 32){
        s = (l < 8) ? shs[l] : 0.f;
        q = (l < 8) ? shq[l] : 0.f;
        s = warpSum(s); q = warpSum(q);
        if (l == 0){
            float mean = s * (1.f / 16384.f);
            float var  = q * (1.f / 16384.f) - mean * mean;
            stats[2 * blockIdx.x]     = mean;
            stats[2 * blockIdx.x + 1] = rsqrtf(var + 1e-6f);
        }
    }
}

// ---------------- groupnorm apply + transpose ----------------
__global__ void gn_apply_t_k(const float* __restrict__ x, const float* __restrict__ stats,
                             const float* __restrict__ gs, const float* __restrict__ gb,
                             float* __restrict__ out){
    __shared__ float tile[32][33];
    int b = blockIdx.z, c0 = blockIdx.y * 32, p0 = blockIdx.x * 32;
    int tx = threadIdx.x, ty = threadIdx.y;
    #pragma unroll
    for (int r = 0; r < 4; r++){
        int c = c0 + ty + r * 8;
        float v = x[((long)b * CC + c) * SS + p0 + tx];
        int grp = b * 32 + (c >> 4);
        v = (v - stats[2 * grp]) * stats[2 * grp + 1] * gs[c] + gb[c];
        tile[ty + r * 8][tx] = v;
    }
    __syncthreads();
    #pragma unroll
    for (int r = 0; r < 4; r++){
        int p = p0 + ty + r * 8;
        out[((long)b * SS + p) * CC + c0 + tx] = tile[tx][ty + r * 8];
    }
}

// ---------------- final transpose + x_in residual ----------------
__global__ void out_add_t_k(const float* __restrict__ z, const float* __restrict__ x,
                            float* __restrict__ out){
    __shared__ float tile[32][33];
    int b = blockIdx.z, c0 = blockIdx.y * 32, p0 = blockIdx.x * 32;
    int tx = threadIdx.x, ty = threadIdx.y;
    #pragma unroll
    for (int r = 0; r < 4; r++){
        int p = p0 + ty + r * 8;
        tile[ty + r * 8][tx] = z[((long)b * SS + p) * CC + c0 + tx];
    }
    __syncthreads();
    #pragma unroll
    for (int r = 0; r < 4; r++){
        int c = c0 + ty + r * 8;
        long o = ((long)b * CC + c) * SS + p0 + tx;
        out[o] = tile[tx][ty + r * 8] + x[o];
    }
}

// ---------------- layernorm ----------------
__global__ void layernorm_k(const float* __restrict__ in, const float* __restrict__ sc,
                            const float* __restrict__ bi, float* __restrict__ out){
    long row = blockIdx.x;
    const float4* x4 = (const float4*)(in + row * CC);
    float4 xv = x4[threadIdx.x];
    float s = xv.x + xv.y + xv.z + xv.w;
    float q = xv.x*xv.x + xv.y*xv.y + xv.z*xv.z + xv.w*xv.w;
    __shared__ float shs[4], shq[4];
    s = warpSum(s); q = warpSum(q);
    int w = threadIdx.x >> 5, l = threadIdx.x & 31;
    if (l == 0){ shs[w] = s; shq[w] = q; }
    __syncthreads();
    if (threadIdx.x < 32){
        float a = (l < 4) ? shs[l] : 0.f;
        float b2 = (l < 4) ? shq[l] : 0.f;
        a = warpSum(a); b2 = warpSum(b2);
        if (l == 0){ shs[0] = a; shq[0] = b2; }
    }
    __syncthreads();
    float mean = shs[0] * (1.f / 512.f);
    float rstd = rsqrtf(shq[0] * (1.f / 512.f) - mean * mean + 1e-5f);
    float4 sv = ((const float4*)sc)[threadIdx.x];
    float4 bv = ((const float4*)bi)[threadIdx.x];
    float4 o;
    o.x = (xv.x - mean) * rstd * sv.x + bv.x;
    o.y = (xv.y - mean) * rstd * sv.y + bv.y;
    o.z = (xv.z - mean) * rstd * sv.z + bv.z;
    o.w = (xv.w - mean) * rstd * sv.w + bv.w;
    ((float4*)(out + row * CC))[threadIdx.x] = o;
}

// =====================================================================
// Flash attention (tf32 mma, online softmax) — unchanged from R6 (passing)
// =====================================================================
template<int TKV, int KVLEN, int NTILES, int NSTAGE>
__global__ void flash_k(const float* __restrict__ Q, const float* __restrict__ K,
                        const float* __restrict__ V, float* __restrict__ O,
                        long kv_bstride){
    constexpr int NT = TKV / 8;
    constexpr int LQ = 68, LK = 68, LV = 72, LP = TKV + 4;
    extern __shared__ float sm[];
    float* Qs = sm;
    float* Ks = sm + 128 * LQ;
    float* Vs = Ks + NSTAGE * TKV * LK;
    float* Pall = Vs + NSTAGE * TKV * LV;

    int tid = threadIdx.x;
    int w = tid >> 5, lane = tid & 31;
    int g = lane >> 2, tg = lane & 3;
    int qt = blockIdx.x;
    int b = blockIdx.y / NHH, h = blockIdx.y % NHH;

    const float* Qb = Q + ((long)(b * SS + qt * 128)) * CC + h * DHH;
    const float* Kb = K + (long)b * kv_bstride + h * DHH;
    const float* Vb = V + (long)b * kv_bstride + h * DHH;

    auto loadQ = [&](){
        #pragma unroll
        for (int i = 0; i < 8; i++){
            int c = tid + i * 256;
            int row = c >> 4, d4 = (c & 15) << 2;
            cp16(Qs + row * LQ + d4, Qb + (long)row * CC + d4, 16);
        }
    };
    auto loadKV = [&](int s, int t){
        constexpr int CH = TKV * 16;
        #pragma unroll
        for (int i = 0; i < CH / 256; i++){
            int c = tid + i * 256;
            int row = c >> 4, d4 = (c & 15) << 2;
            int r = t * TKV + row;
            int by = (r < KVLEN) ? 16 : 0;
            const float* ksrc = by ? (Kb + (long)r * CC + d4) : Kb;
            const float* vsrc = by ? (Vb + (long)r * CC + d4) : Vb;
            cp16(Ks + s * TKV * LK + row * LK + d4, ksrc, by);
            cp16(Vs + s * TKV * LV + row * LV + d4, vsrc, by);
        }
    };

    loadQ(); loadKV(0, 0); cp_commit();
    if (NTILES > 1){ loadKV(1, 1); cp_commit(); }

    float qa[8][4];
    float oacc[8][4];
    #pragma unroll
    for (int j = 0; j < 8; j++)
        #pragma unroll
        for (int r = 0; r < 4; r++) oacc[j][r] = 0.f;
    float m0 = -1e30f, m1 = -1e30f, l0 = 0.f, l1 = 0.f;
    float* Ps = Pall + w * 16 * LP;

    for (int t = 0; t < NTILES; t++){
        if (t + 1 < NTILES) cp_wait<1>(); else cp_wait<0>();
        __syncthreads();
        if (t == 0){
            const float* qsw = Qs + w * 16 * LQ;
            #pragma unroll
            for (int kk = 0; kk < 8; kk++){
                qa[kk][0] = qsw[(g    ) * LQ + kk * 8 + tg    ];
                qa[kk][1] = qsw[(g + 8) * LQ + kk * 8 + tg    ];
                qa[kk][2] = qsw[(g    ) * LQ + kk * 8 + tg + 4];
                qa[kk][3] = qsw[(g + 8) * LQ + kk * 8 + tg + 4];
            }
            __syncwarp();
        }
        const float* Kt = Ks + (t % NSTAGE) * TKV * LK;
        const float* Vt = Vs + (t % NSTAGE) * TKV * LV;

        float sacc[NT][4];
        #pragma unroll
        for (int j = 0; j < NT; j++)
            #pragma unroll
            for (int r = 0; r < 4; r++) sacc[j][r] = 0.f;
        #pragma unroll
        for (int j = 0; j < NT; j++){
            const float* krow = Kt + (j * 8 + g) * LK;
            #pragma unroll
            for (int kk = 0; kk < 8; kk++)
                mma_tf32f(sacc[j], qa[kk], krow[kk * 8 + tg], krow[kk * 8 + tg + 4]);
        }
        if (KVLEN < NTILES * TKV && t == NTILES - 1){
            #pragma unroll
            for (int j = 0; j < NT; j++){
                int col = t * TKV + j * 8 + 2 * tg;
                if (col     >= KVLEN){ sacc[j][0] = -1e30f; sacc[j][2] = -1e30f; }
                if (col + 1 >= KVLEN){ sacc[j][1] = -1e30f; sacc[j][3] = -1e30f; }
            }
        }
        float rm0 = -1e30f, rm1 = -1e30f;
        #pragma unroll
        for (int j = 0; j < NT; j++){
            rm0 = fmaxf(rm0, fmaxf(sacc[j][0], sacc[j][1]));
            rm1 = fmaxf(rm1, fmaxf(sacc[j][2], sacc[j][3]));
        }
        rm0 = fmaxf(rm0, __shfl_xor_sync(0xffffffffu, rm0, 1));
        rm0 = fmaxf(rm0, __shfl_xor_sync(0xffffffffu, rm0, 2));
        rm1 = fmaxf(rm1, __shfl_xor_sync(0xffffffffu, rm1, 1));
        rm1 = fmaxf(rm1, __shfl_xor_sync(0xffffffffu, rm1, 2));
        float mn0 = fmaxf(m0, rm0), mn1 = fmaxf(m1, rm1);
        float a0 = __expf(m0 - mn0), a1 = __expf(m1 - mn1);
        float rs0 = 0.f, rs1 = 0.f;
        #pragma unroll
        for (int j = 0; j < NT; j++){
            sacc[j][0] = __expf(sacc[j][0] - mn0);
            sacc[j][1] = __expf(sacc[j][1] - mn0);
            sacc[j][2] = __expf(sacc[j][2] - mn1);
            sacc[j][3] = __expf(sacc[j][3] - mn1);
            rs0 += sacc[j][0] + sacc[j][1];
            rs1 += sacc[j][2] + sacc[j][3];
        }
        rs0 += __shfl_xor_sync(0xffffffffu, rs0, 1);
        rs0 += __shfl_xor_sync(0xffffffffu, rs0, 2);
        rs1 += __shfl_xor_sync(0xffffffffu, rs1, 1);
        rs1 += __shfl_xor_sync(0xffffffffu, rs1, 2);
        l0 = l0 * a0 + rs0;  l1 = l1 * a1 + rs1;
        m0 = mn0;  m1 = mn1;
        #pragma unroll
        for (int jn = 0; jn < 8; jn++){
            oacc[jn][0] *= a0; oacc[jn][1] *= a0;
            oacc[jn][2] *= a1; oacc[jn][3] *= a1;
        }
        #pragma unroll
        for (int j = 0; j < NT; j++){
            Ps[(g    ) * LP + j * 8 + 2 * tg    ] = sacc[j][0];
            Ps[(g    ) * LP + j * 8 + 2 * tg + 1] = sacc[j][1];
            Ps[(g + 8) * LP + j * 8 + 2 * tg    ] = sacc[j][2];
            Ps[(g + 8) * LP + j * 8 + 2 * tg + 1] = sacc[j][3];
        }
        __syncwarp();
        #pragma unroll
        for (int kk = 0; kk < NT; kk++){
            float pa[4];
            pa[0] = Ps[(g    ) * LP + kk * 8 + tg    ];
            pa[1] = Ps[(g + 8) * LP + kk * 8 + tg    ];
            pa[2] = Ps[(g    ) * LP + kk * 8 + tg + 4];
            pa[3] = Ps[(g + 8) * LP + kk * 8 + tg + 4];
            #pragma unroll
            for (int jn = 0; jn < 8; jn++){
                float vb0 = Vt[(kk * 8 + tg    ) * LV + jn * 8 + g];
                float vb1 = Vt[(kk * 8 + tg + 4) * LV + jn * 8 + g];
                mma_tf32f(oacc[jn], pa, vb0, vb1);
            }
        }
        __syncthreads();
        if (t + 2 < NTILES) loadKV(t % 2, t + 2);
        cp_commit();
    }

    float inv0 = 1.f / l0, inv1 = 1.f / l1;
    float* Ob = O + ((long)(b * SS + qt * 128 + w * 16)) * CC + h * DHH;
    #pragma unroll
    for (int jn = 0; jn < 8; jn++){
        int col = jn * 8 + 2 * tg;
        Ob[(long)(g    ) * CC + col    ] = oacc[jn][0] * inv0;
        Ob[(long)(g    ) * CC + col + 1] = oacc[jn][1] * inv0;
        Ob[(long)(g + 8) * CC + col    ] = oacc[jn][2] * inv1;
        Ob[(long)(g + 8) * CC + col + 1] = oacc[jn][3] * inv1;
    }
}

// =====================================================================
// NN tf32 GEMM: BM=128, BN=128, 4 warps of 64x64, BK=32, 3-stage cp.async.
// 128 threads + ~105KB smem -> 2 blocks/SM (was reg-capped at 1).
// Optional GEGLU epilogue: B cols [0,64) map to w1 col c0h+nc (u panel),
// cols [64,128) map to w1 col c0h+nc-64+2048 (gate panel); epilogue
// exchanges gelu(gate) through smem and writes u*gelu(gate).
// =====================================================================
constexpr int GK_LA = 36;                 // A row stride (BK+4)
constexpr int GK_LB = 136;                // B row stride (BN+8)
constexpr int GK_AW = 128 * GK_LA;        // 4608
constexpr int GK_BW = 32 * GK_LB;         // 4352
constexpr int GK_SMEM = 3 * (GK_AW + GK_BW) * 4;   // 107,520 B

template<bool GEGLU>
__global__ void mma_gemm_k(const float* __restrict__ A, const float* __restrict__ Bm,
                           const float* __restrict__ bias, const float* __restrict__ res,
                           float* __restrict__ C,
                           int M, int N, int K, int lda, int ldb, int ldc){
    constexpr int BK = 32, STAGES = 3;
    extern __shared__ float sm[];
    float* As = sm;
    float* Bs = sm + STAGES * GK_AW;

    int tid  = threadIdx.x;
    int warp = tid >> 5, lane = tid & 31;
    int g  = lane >> 2;
    int tg = lane & 3;
    int wm = (warp & 1) * 64;
    int wn = (warp >> 1) * 64;
    int row0 = blockIdx.y * 128;
    int col0 = GEGLU ? 0 : blockIdx.x * 128;     // GEGLU: col handled via remap
    int c0h  = blockIdx.x * 64;                  // GEGLU: output col base

    float acc[4][8][4];
    #pragma unroll
    for (int i = 0; i < 4; i++)
        #pragma unroll
        for (int j = 0; j < 8; j++)
            #pragma unroll
            for (int r = 0; r < 4; r++) acc[i][j][r] = 0.f;

    auto loadA = [&](int s, int kt){
        float* base = As + s * GK_AW;
        #pragma unroll
        for (int it = 0; it < 8; it++){          // 1024 chunks / 128 threads
            int c = tid + it * 128;
            int m  = c >> 3;
            int kc = (c & 7) << 2;
            int gm = row0 + m, gk = kt + kc;
            int bytes = (gm < M && gk < K) ? 16 : 0;
            const float* src = bytes ? (A + (long)gm * lda + gk) : A;
            cp16(base + m * GK_LA + kc, src, bytes);
        }
    };
    auto loadB = [&](int s, int kt){
        float* base = Bs + s * GK_BW;
        #pragma unroll
        for (int it = 0; it < 8; it++){          // 32*32 chunks / 128 threads
            int c = tid + it * 128;
            int kr = c >> 5;
            int nc = (c & 31) << 2;
            int gk = kt + kr;
            int gn;
            if (GEGLU) gn = c0h + (nc & 63) + ((nc >= 64) ? 2048 : 0);
            else       gn = col0 + nc;
            int bytes = (gk < K && gn < N) ? 16 : 0;
            const float* src = bytes ? (Bm + (long)gk * ldb + gn) : Bm;
            cp16(base + kr * GK_LB + nc, src, bytes);
        }
    };
    auto compute = [&](int s){
        const float* Ab = As + s * GK_AW;
        const float* Bb = Bs + s * GK_BW;
        #pragma unroll
        for (int ks = 0; ks < BK; ks += 8){
            uint32_t bf[8][2];
            #pragma unroll
            for (int j = 0; j < 8; j++){
                bf[j][0] = __float_as_uint(Bb[(ks + tg    ) * GK_LB + wn + j * 8 + g]);
                bf[j][1] = __float_as_uint(Bb[(ks + tg + 4) * GK_LB + wn + j * 8 + g]);
            }
            #pragma unroll
            for (int i = 0; i < 4; i++){
                int mr = wm + i * 16 + g;
                uint32_t af[4];
                af[0] = __float_as_uint(Ab[(mr    ) * GK_LA + ks + tg]);
                af[1] = __float_as_uint(Ab[(mr + 8) * GK_LA + ks + tg]);
                af[2] = __float_as_uint(Ab[(mr    ) * GK_LA + ks + tg + 4]);
                af[3] = __float_as_uint(Ab[(mr + 8) * GK_LA + ks + tg + 4]);
                #pragma unroll
                for (int j = 0; j < 8; j++)
                    mma_tf32(acc[i][j], af, bf[j]);
            }
        }
    };

    int nk = (K + BK - 1) / BK;
    #pragma unroll
    for (int s = 0; s < STAGES - 1; s++){
        if (s < nk){ loadA(s, s * BK); loadB(s, s * BK); }
        cp_commit();
    }
    for (int t = 0; t < nk; t++){
        cp_wait<STAGES - 2>();
        __syncthreads();
        int tn = t + STAGES - 1;
        if (tn < nk){ loadA(tn % STAGES, tn * BK); loadB(tn % STAGES, tn * BK); }
        cp_commit();
        compute(t % STAGES);
    }

    if (!GEGLU){
        // plain epilogue: +bias, +res, float2 stores
        #pragma unroll
        for (int i = 0; i < 4; i++){
            int r0 = row0 + wm + i * 16 + g;
            int r1 = r0 + 8;
            #pragma unroll
            for (int j = 0; j < 8; j++){
                int c0 = col0 + wn + j * 8 + 2 * tg;
                float* a4 = acc[i][j];
                float b0 = 0.f, b1v = 0.f;
                if (bias){ b0 = bias[c0]; b1v = bias[c0 + 1]; }
                if (r0 < M){
                    float2 v = {a4[0] + b0, a4[1] + b1v};
                    if (res){
                        float2 rr = *(const float2*)&res[(long)r0 * ldc + c0];
                        v.x += rr.x; v.y += rr.y;
                    }
                    *(float2*)&C[(long)r0 * ldc + c0] = v;
                }
                if (r1 < M){
                    float2 v = {a4[2] + b0, a4[3] + b1v};
                    if (res){
                        float2 rr = *(const float2*)&res[(long)r1 * ldc + c0];
                        v.x += rr.x; v.y += rr.y;
                    }
                    *(float2*)&C[(long)r1 * ldc + c0] = v;
                }
            }
        }
    } else {
        // GEGLU epilogue: gate warps (wn=64) write gelu(gate+b) to smem,
        // u warps (wn=0) multiply and emit g = (u+b) * gelu_exchange.
        constexpr int LE = 68;
        float* ex = sm;                           // 128 x 68 (pipeline smem, now free)
        __syncthreads();                          // all mainloop smem reads done
        if (wn == 64){
            #pragma unroll
            for (int i = 0; i < 4; i++){
                int lr0 = wm + i * 16 + g, lr1 = lr0 + 8;
                #pragma unroll
                for (int j = 0; j < 8; j++){
                    int gc = j * 8 + 2 * tg;      // 0..62
                    float bg0 = bias[c0h + gc + 2048];
                    float bg1 = bias[c0h + gc + 1 + 2048];
                    ex[lr0 * LE + gc    ] = gelu_exact(acc[i][j][0] + bg0);
                    ex[lr0 * LE + gc + 1] = gelu_exact(acc[i][j][1] + bg1);
                    ex[lr1 * LE + gc    ] = gelu_exact(acc[i][j][2] + bg0);
                    ex[lr1 * LE + gc + 1] = gelu_exact(acc[i][j][3] + bg1);
                }
            }
        }
        __syncthreads();
        if (wn == 0){
            #pragma unroll
            for (int i = 0; i < 4; i++){
                int lr0 = wm + i * 16 + g, lr1 = lr0 + 8;
                long gr0 = row0 + lr0, gr1 = row0 + lr1;
                #pragma unroll
                for (int j = 0; j < 8; j++){
                    int lc = j * 8 + 2 * tg;
                    float bu0 = bias[c0h + lc], bu1 = bias[c0h + lc + 1];
                    float2 v0 = {(acc[i][j][0] + bu0) * ex[lr0 * LE + lc],
                                 (acc[i][j][1] + bu1) * ex[lr0 * LE + lc + 1]};
                    float2 v1 = {(acc[i][j][2] + bu0) * ex[lr1 * LE + lc],
                                 (acc[i][j][3] + bu1) * ex[lr1 * LE + lc + 1]};
                    *(float2*)&C[gr0 * ldc + c0h + lc] = v0;
                    *(float2*)&C[gr1 * ldc + c0h + lc] = v1;
                }
            }
        }
    }
}

// ---------------- launch helpers ----------------
static void gemm_big(const float* A, const float* W, const float* bias, const float* res,
                     float* C, int M, int N, int K, int lda, int ldb, int ldc){
    cudaFuncSetAttribute(mma_gemm_k<false>,
                         cudaFuncAttributeMaxDynamicSharedMemorySize, GK_SMEM);
    dim3 g((N + 127) / 128, (M + 127) / 128, 1);
    mma_gemm_k<false><<<g, 128, GK_SMEM>>>(A, W, bias, res, C, M, N, K, lda, ldb, ldc);
}
static void gemm_geglu(const float* A, const float* W1, const float* b1, float* G){
    cudaFuncSetAttribute(mma_gemm_k<true>,
                         cudaFuncAttributeMaxDynamicSharedMemorySize, GK_SMEM);
    dim3 g(2048 / 64, MM / 128, 1);
    mma_gemm_k<true><<<g, 128, GK_SMEM>>>(A, W1, b1, nullptr, G, MM, 4096, CC,
                                          CC, 4096, 2048);
}

extern "C" void kernel_launch(void* const* d_in, const int* in_sizes, int n_in,
                              void* d_out, int out_size){
    (void)in_sizes; (void)n_in; (void)out_size;
    const float* x      = (const float*)d_in[0];
    const float* cond   = (const float*)d_in[1];
    const float* gn_s   = (const float*)d_in[2];
    const float* gn_b   = (const float*)d_in[3];
    const float* pin_w  = (const float*)d_in[4];
    const float* pin_b  = (const float*)d_in[5];
    const float* pout_w = (const float*)d_in[6];
    const float* pout_b = (const float*)d_in[7];
    const float* ln1_s  = (const float*)d_in[8];
    const float* ln1_b  = (const float*)d_in[9];
    const float* sa_wq  = (const float*)d_in[10];
    const float* sa_wk  = (const float*)d_in[11];
    const float* sa_wv  = (const float*)d_in[12];
    const float* sa_wo  = (const float*)d_in[13];
    const float* sa_bo  = (const float*)d_in[14];
    const float* ln2_s  = (const float*)d_in[15];
    const float* ln2_b  = (const float*)d_in[16];
    const float* ca_wq  = (const float*)d_in[17];
    const float* ca_wk  = (const float*)d_in[18];
    const float* ca_wv  = (const float*)d_in[19];
    const float* ca_wo  = (const float*)d_in[20];
    const float* ca_bo  = (const float*)d_in[21];
    const float* ln3_s  = (const float*)d_in[22];
    const float* ln3_b  = (const float*)d_in[23];
    const float* ff_w1  = (const float*)d_in[24];
    const float* ff_b1  = (const float*)d_in[25];
    const float* ff_w2  = (const float*)d_in[26];
    const float* ff_b2  = (const float*)d_in[27];
    float* out = (float*)d_out;

    float *p_t, *p_tn, *p_q, *p_k, *p_v, *p_ao, *p_gg, *p_stats;
    cudaGetSymbolAddress((void**)&p_t,    g_t);
    cudaGetSymbolAddress((void**)&p_tn,   g_tn);
    cudaGetSymbolAddress((void**)&p_q,    g_q);
    cudaGetSymbolAddress((void**)&p_k,    g_k);
    cudaGetSymbolAddress((void**)&p_v,    g_v);
    cudaGetSymbolAddress((void**)&p_ao,   g_ao);
    cudaGetSymbolAddress((void**)&p_gg,   g_gg);
    cudaGetSymbolAddress((void**)&p_stats,g_stats);

    constexpr int SM_SELF  = (128 * 68 + 2 * 64 * 68 + 2 * 64 * 72 + 128 * (64 + 4)) * 4;
    constexpr int SM_CROSS = (128 * 68 + 80 * 68 + 80 * 72 + 128 * (80 + 4)) * 4;
    cudaFuncSetAttribute(flash_k<64, 1024, 16, 2>,
                         cudaFuncAttributeMaxDynamicSharedMemorySize, SM_SELF);
    cudaFuncSetAttribute(flash_k<80, 77, 1, 1>,
                         cudaFuncAttributeMaxDynamicSharedMemorySize, SM_CROSS);

    gn_stats_k<<<BB * 32, 256>>>(x, p_stats);
    {
        dim3 g(SS / 32, CC / 32, BB);
        gn_apply_t_k<<<g, dim3(32, 8)>>>(x, p_stats, gn_s, gn_b, p_tn);
    }
    gemm_big(p_tn, pin_w, pin_b, nullptr, p_t, MM, CC, CC, CC, CC, CC);

    for (int l = 0; l < 2; l++){
        const float* wq = sa_wq + (long)l * CC * CC;
        const float* wk = sa_wk + (long)l * CC * CC;
        const float* wv = sa_wv + (long)l * CC * CC;
        const float* wo = sa_wo + (long)l * CC * CC;
        const float* bo = sa_bo + (long)l * CC;
        const float* cwq = ca_wq + (long)l * CC * CC;
        const float* cwk = ca_wk + (long)l * DCC * CC;
        const float* cwv = ca_wv + (long)l * DCC * CC;
        const float* cwo = ca_wo + (long)l * CC * CC;
        const float* cbo = ca_bo + (long)l * CC;
        const float* w1 = ff_w1 + (long)l * CC * 4096;
        const float* b1 = ff_b1 + (long)l * 4096;
        const float* w2 = ff_w2 + (long)l * 2048 * CC;
        const float* b2 = ff_b2 + (long)l * CC;

        // ---- self-attention ----
        layernorm_k<<<MM, 128>>>(p_t, ln1_s + l * CC, ln1_b + l * CC, p_tn);
        gemm_big(p_tn, wq, nullptr, nullptr, p_q, MM, CC, CC, CC, CC, CC);
        gemm_big(p_tn, wk, nullptr, nullptr, p_k, MM, CC, CC, CC, CC, CC);
        gemm_big(p_tn, wv, nullptr, nullptr, p_v, MM, CC, CC, CC, CC, CC);
        flash_k<64, 1024, 16, 2><<<dim3(SS / 128, BB * NHH), 256, SM_SELF>>>(
            p_q, p_k, p_v, p_ao, (long)SS * CC);
        gemm_big(p_ao, wo, bo, p_t, p_t, MM, CC, CC, CC, CC, CC);

        // ---- cross-attention ----
        layernorm_k<<<MM, 128>>>(p_t, ln2_s + l * CC, ln2_b + l * CC, p_tn);
        gemm_big(p_tn, cwq, nullptr, nullptr, p_q, MM, CC, CC, CC, CC, CC);
        gemm_big(cond, cwk, nullptr, nullptr, p_k, BB * NCC, CC, DCC, DCC, CC, CC);
        gemm_big(cond, cwv, nullptr, nullptr, p_v, BB * NCC, CC, DCC, DCC, CC, CC);
        flash_k<80, 77, 1, 1><<<dim3(SS / 128, BB * NHH), 256, SM_CROSS>>>(
            p_q, p_k, p_v, p_ao, (long)NCC * CC);
        gemm_big(p_ao, cwo, cbo, p_t, p_t, MM, CC, CC, CC, CC, CC);

        // ---- FFN (GEGLU fused into FFN1 epilogue) ----
        layernorm_k<<<MM, 128>>>(p_t, ln3_s + l * CC, ln3_b + l * CC, p_tn);
        gemm_geglu(p_tn, w1, b1, p_gg);
        gemm_big(p_gg, w2, b2, p_t, p_t, MM, CC, 2048, 2048, CC, CC);
    }

    gemm_big(p_t, pout_w, pout_b, nullptr, p_tn, MM, CC, CC, CC, CC, CC);
    {
        dim3 g(SS / 32, CC / 32, BB);
        out_add_t_k<<<g, dim3(32, 8)>>>(p_tn, x, out);
    }
}